// round 12
// baseline (speedup 1.0000x reference)
#include <cuda_runtime.h>
#include <cuda_fp16.h>
#include <math.h>
#include <stdint.h>

#define N_USERS 60000
#define N_ITEMS 40000
#define NU      60001
#define NND     100002
#define NND4    ((NND + 3) / 4)
#define D       64
#define ND64    (NND * 64)
#define E_GLOBAL 1000000
#define E_BEH    500000
#define E_TOT   (E_GLOBAL + 3 * E_BEH)
#define BATCH    4096

#define SCB 512
#define NCH ((NND + SCB - 1) / SCB)

/* ---------------- scratch ---------------- */
__device__ __align__(16) __half g_hw[ND64];       /* global dinv*h@W (fp16) */
__device__ __align__(16) __half g_hwb[3][ND64];   /* behavioral dinv*h@W (fp16) */
__device__ __align__(16) __half g_b16[ND64];      /* fp16 GEMM input "base" */
__device__ __align__(16) __half g_h16[ND64];      /* fp16 global h */
__device__ __align__(16) __half g_hb16[3][ND64];  /* fp16 behavioral h */
__device__ __align__(16) __half g_beh16[3][ND64]; /* fp16 behavioral res */
__device__ float  g_base[ND64];                   /* fp32 global res */
__device__ float  g_w[3][ND64];                   /* combined uw/iw (marked rows) */
__device__ float  g_dinv[4 * NND];
__device__ int    g_deg[4 * NND];
__device__ int    g_part[4 * NCH];
__device__ int    g_ptr[4 * (NND + 1)];
__device__ int    g_cnt[4 * NND];
__device__ int    g_csr[E_TOT];
__device__ unsigned char g_mark[NND];
__device__ float  g_sc[2];

/* ---------------- helpers ---------------- */
__device__ __forceinline__ float warp_sum(float v) {
#pragma unroll
    for (int o = 16; o; o >>= 1) v += __shfl_xor_sync(0xffffffffu, v, o);
    return v;
}
__device__ __forceinline__ float hsum8(float v) {
#pragma unroll
    for (int o = 4; o; o >>= 1) v += __shfl_xor_sync(0xffffffffu, v, o);
    return v;
}
__device__ __forceinline__ uint32_t f2h2(float2 v) {
    __half2 h = __floats2half2_rn(v.x, v.y);
    return *(uint32_t*)&h;
}
__device__ __forceinline__ float2 h22f2(uint32_t u) {
    return __half22float2(*(__half2*)&u);
}
__device__ __forceinline__ uint2 f4h4(float4 v) {
    return make_uint2(f2h2(make_float2(v.x, v.y)), f2h2(make_float2(v.z, v.w)));
}

__device__ __forceinline__ void mma16816(float4& c, uint32_t a0, uint32_t a1,
                                         uint32_t a2, uint32_t a3,
                                         uint32_t b0, uint32_t b1) {
    asm volatile(
        "mma.sync.aligned.m16n8k16.row.col.f32.f16.f16.f32 "
        "{%0,%1,%2,%3}, {%4,%5,%6,%7}, {%8,%9}, {%0,%1,%2,%3};"
        : "+f"(c.x), "+f"(c.y), "+f"(c.z), "+f"(c.w)
        : "r"(a0), "r"(a1), "r"(a2), "r"(a3), "r"(b0), "r"(b1));
}

/* ---------------- tiny zero ---------------- */
__global__ void zero0_k(float* out) {
    if (threadIdx.x < 2) g_sc[threadIdx.x] = 0.0f;
    if (threadIdx.x == 2) out[0] = 0.0f;
}

/* ------- concat + fused sumsq + fp16 copy + zero g_deg/g_mark ------- */
__global__ void concat_k(const float* __restrict__ ue, const float* __restrict__ ie) {
    int t = blockIdx.x * blockDim.x + threadIdx.x;
    if (t < 4 * NND) g_deg[t] = 0;
    if (t < NND) g_mark[t] = 0;
    float su = 0.0f, si = 0.0f;
    if (t < NND * 16) {
        int node = t >> 4, q = t & 15;
        float4 v;
        if (node < NU) {
            v = ((const float4*)ue)[node * 16 + q];
            su = v.x * v.x + v.y * v.y + v.z * v.z + v.w * v.w;
        } else {
            v = ((const float4*)ie)[(node - NU) * 16 + q];
            si = v.x * v.x + v.y * v.y + v.z * v.z + v.w * v.w;
        }
        ((float4*)g_base)[t] = v;
        ((uint2*)g_b16)[t] = f4h4(v);
    }
    su = warp_sum(su);
    si = warp_sum(si);
    __shared__ float smu[8], smi[8];
    int w = threadIdx.x >> 5, l = threadIdx.x & 31;
    if (l == 0) { smu[w] = su; smi[w] = si; }
    __syncthreads();
    if (threadIdx.x == 0) {
        float a = 0.f, b = 0.f;
#pragma unroll
        for (int q = 0; q < 8; q++) { a += smu[q]; b += smi[q]; }
        if (a != 0.f) atomicAdd(&g_sc[0], a);
        if (b != 0.f) atomicAdd(&g_sc[1], b);
    }
}

/* ---------------- mark nodes needed by the loss ---------------- */
__global__ void mark_k(const int* __restrict__ bd) {
    int t = blockIdx.x * blockDim.x + threadIdx.x;
    if (t >= BATCH * 9) return;
    int k = t / 9, r = t - k * 9;
    int i = r / 3, c = r - i * 3;
    int val = bd[k * 9 + i * 3 + c];
    if (c == 0) g_mark[val] = 1;
    else        g_mark[NU + val] = 1;
}

/* ---------------- degrees, 8 edges per thread (2x int4) ---------------- */
__global__ void degcnt_all_k(const int* __restrict__ aei, const int* __restrict__ bei) {
    int q = blockIdx.x * blockDim.x + threadIdx.x;   /* octet index */
    if (q >= E_TOT / 8) return;
    int4 a, b;
    int g;
    if (q < E_GLOBAL / 8) {
        g = 0;
        a = ((const int4*)(aei + E_GLOBAL))[2 * q];
        b = ((const int4*)(aei + E_GLOBAL))[2 * q + 1];
    } else {
        int r = q - E_GLOBAL / 8;
        int bb_ = r / (E_BEH / 8), o = r - bb_ * (E_BEH / 8);
        g = 1 + bb_;
        const int* p = bei + (bb_ * 2 + 1) * E_BEH;
        a = ((const int4*)p)[2 * o];
        b = ((const int4*)p)[2 * o + 1];
    }
    int* deg = g_deg + g * NND;
    atomicAdd(&deg[a.x], 1); atomicAdd(&deg[a.y], 1);
    atomicAdd(&deg[a.z], 1); atomicAdd(&deg[a.w], 1);
    atomicAdd(&deg[b.x], 1); atomicAdd(&deg[b.y], 1);
    atomicAdd(&deg[b.z], 1); atomicAdd(&deg[b.w], 1);
}

/* ---------------- CSR build ---------------- */
__global__ __launch_bounds__(SCB) void part_k() {
    __shared__ int sm[SCB];
    int b = blockIdx.x;
    int g = b / NCH, ch = b % NCH;
    int idx = ch * SCB + threadIdx.x;
    int v = (idx < NND) ? g_deg[g * NND + idx] : 0;
    sm[threadIdx.x] = v;
    __syncthreads();
    for (int o = SCB / 2; o; o >>= 1) {
        if (threadIdx.x < o) sm[threadIdx.x] += sm[threadIdx.x + o];
        __syncthreads();
    }
    if (threadIdx.x == 0) g_part[b] = sm[0];
}

__global__ __launch_bounds__(256) void scanpart_k() {
    __shared__ int sm[256];
    for (int g = 0; g < 4; g++) {
        int v = (threadIdx.x < NCH) ? g_part[g * NCH + threadIdx.x] : 0;
        sm[threadIdx.x] = v;
        __syncthreads();
        for (int o = 1; o < 256; o <<= 1) {
            int a = (threadIdx.x >= o) ? sm[threadIdx.x - o] : 0;
            __syncthreads();
            sm[threadIdx.x] += a;
            __syncthreads();
        }
        if (threadIdx.x < NCH) g_part[g * NCH + threadIdx.x] = sm[threadIdx.x] - v;
        if (threadIdx.x == NCH - 1) g_ptr[g * (NND + 1) + NND] = sm[threadIdx.x];
        __syncthreads();
    }
}

/* scan + fused dinv */
__global__ __launch_bounds__(SCB) void scan_k() {
    __shared__ int sm[SCB];
    int b = blockIdx.x;
    int g = b / NCH, ch = b % NCH;
    int idx = ch * SCB + threadIdx.x;
    int v = (idx < NND) ? g_deg[g * NND + idx] : 0;
    sm[threadIdx.x] = v;
    __syncthreads();
    for (int o = 1; o < SCB; o <<= 1) {
        int add = (threadIdx.x >= o) ? sm[threadIdx.x - o] : 0;
        __syncthreads();
        sm[threadIdx.x] += add;
        __syncthreads();
    }
    int excl = sm[threadIdx.x] - v + g_part[b];
    if (idx < NND) {
        g_ptr[g * (NND + 1) + idx] = excl;
        g_cnt[g * NND + idx]       = excl;
        g_dinv[g * NND + idx]      = (v > 0) ? rsqrtf((float)v) : 0.0f;
    }
}

/* ---------------- fill, 8 edges per thread ---------------- */
__global__ void fill_all_k(const int* __restrict__ aei, const int* __restrict__ bei) {
    int q = blockIdx.x * blockDim.x + threadIdx.x;
    if (q >= E_TOT / 8) return;
    int4 s0, s1, d0, d1;
    int g, base;
    if (q < E_GLOBAL / 8) {
        g = 0;
        base = 0;
        s0 = ((const int4*)aei)[2 * q];
        s1 = ((const int4*)aei)[2 * q + 1];
        d0 = ((const int4*)(aei + E_GLOBAL))[2 * q];
        d1 = ((const int4*)(aei + E_GLOBAL))[2 * q + 1];
    } else {
        int r = q - E_GLOBAL / 8;
        int bb_ = r / (E_BEH / 8), o = r - bb_ * (E_BEH / 8);
        g = 1 + bb_;
        base = E_GLOBAL + bb_ * E_BEH;
        const int* ps = bei + (bb_ * 2) * E_BEH;
        const int* pd = bei + (bb_ * 2 + 1) * E_BEH;
        s0 = ((const int4*)ps)[2 * o];
        s1 = ((const int4*)ps)[2 * o + 1];
        d0 = ((const int4*)pd)[2 * o];
        d1 = ((const int4*)pd)[2 * o + 1];
    }
    int* cnt = g_cnt + g * NND;
    int* csr = g_csr + base;
    csr[atomicAdd(&cnt[d0.x], 1)] = s0.x;
    csr[atomicAdd(&cnt[d0.y], 1)] = s0.y;
    csr[atomicAdd(&cnt[d0.z], 1)] = s0.z;
    csr[atomicAdd(&cnt[d0.w], 1)] = s0.w;
    csr[atomicAdd(&cnt[d1.x], 1)] = s1.x;
    csr[atomicAdd(&cnt[d1.y], 1)] = s1.y;
    csr[atomicAdd(&cnt[d1.z], 1)] = s1.z;
    csr[atomicAdd(&cnt[d1.w], 1)] = s1.w;
}

/* --------- HMMA GEMM: HW = fp16(dinv * (A16 @ W)), 128 rows/CTA --------- */
#define SAS 72
__device__ __forceinline__ void gemm_body(const __half* __restrict__ A16,
                                          const float* __restrict__ W,
                                          __half* __restrict__ HW, int row0,
                                          const float* __restrict__ dv) {
    __shared__ __half sA[128 * SAS];
    __shared__ __half sWt[64 * SAS];
    int tid = threadIdx.x;

#pragma unroll
    for (int i = 0; i < 4; i++) {
        int idx = tid + i * 256;
        int r = idx >> 3, c8 = idx & 7;
        uint4 u = make_uint4(0u, 0u, 0u, 0u);
        int row = row0 + r;
        if (row < NND) u = ((const uint4*)A16)[row * 8 + c8];
        *(uint4*)(sA + r * SAS + c8 * 8) = u;
    }
#pragma unroll
    for (int i = 0; i < 4; i++) {
        int idx = tid + i * 256;
        int k = idx >> 4, n4 = (idx & 15) * 4;
        float4 w = ((const float4*)W)[idx];
        sWt[(n4 + 0) * SAS + k] = __float2half_rn(w.x);
        sWt[(n4 + 1) * SAS + k] = __float2half_rn(w.y);
        sWt[(n4 + 2) * SAS + k] = __float2half_rn(w.z);
        sWt[(n4 + 3) * SAS + k] = __float2half_rn(w.w);
    }
    __syncthreads();

    int wid = tid >> 5, lane = tid & 31;
    int gq = lane >> 2, tg = lane & 3;
    int mrow = wid * 16;

    float4 acc[8];
#pragma unroll
    for (int n = 0; n < 8; n++) acc[n] = make_float4(0.f, 0.f, 0.f, 0.f);

#pragma unroll
    for (int ks = 0; ks < 4; ks++) {
        int k0 = ks * 16 + tg * 2;
        uint32_t a0 = *(uint32_t*)(sA + (mrow + gq) * SAS + k0);
        uint32_t a1 = *(uint32_t*)(sA + (mrow + gq + 8) * SAS + k0);
        uint32_t a2 = *(uint32_t*)(sA + (mrow + gq) * SAS + k0 + 8);
        uint32_t a3 = *(uint32_t*)(sA + (mrow + gq + 8) * SAS + k0 + 8);
#pragma unroll
        for (int n = 0; n < 8; n++) {
            uint32_t b0 = *(uint32_t*)(sWt + (n * 8 + gq) * SAS + k0);
            uint32_t b1 = *(uint32_t*)(sWt + (n * 8 + gq) * SAS + k0 + 8);
            mma16816(acc[n], a0, a1, a2, a3, b0, b1);
        }
    }

    int r0 = row0 + mrow + gq;
    int r1 = r0 + 8;
    float s0 = (r0 < NND) ? dv[r0] : 0.0f;
    float s1 = (r1 < NND) ? dv[r1] : 0.0f;
#pragma unroll
    for (int n = 0; n < 8; n++) {
        int col = n * 8 + tg * 2;
        if (r0 < NND)
            *(uint32_t*)(HW + r0 * 64 + col) = f2h2(make_float2(acc[n].x * s0, acc[n].y * s0));
        if (r1 < NND)
            *(uint32_t*)(HW + r1 * 64 + col) = f2h2(make_float2(acc[n].z * s1, acc[n].w * s1));
    }
}

__global__ __launch_bounds__(256) void gemm_k(const float* __restrict__ W, int srcsel) {
    gemm_body(srcsel ? g_h16 : g_b16, W, g_hw, blockIdx.x * 128, g_dinv);
}

__global__ __launch_bounds__(256) void gemm3_k(const float* __restrict__ bW, int l) {
    int b = blockIdx.y;
    const __half* A16 = l ? g_hb16[b] : g_b16;
    gemm_body(A16, bW + (b * 2 + l) * 4096, g_hwb[b], blockIdx.x * 128,
              g_dinv + (1 + b) * NND);
}

/* ------- 8-lane gather core: quarter-warp per node, lane owns 8 cols ------- */
struct F8 { float v[8]; };

__device__ __forceinline__ F8 gather_core8(
    const __half* __restrict__ HW, int csr_base, int g,
    const float* __restrict__ bias, int node, int sub, bool active) {

    const int* ptr = g_ptr + g * (NND + 1);
    const int* csr = g_csr + csr_base;
    const uint4* HW128 = (const uint4*)HW;   /* 8 uint4 per 64-half row */
    int beg = 0, end = 0;
    if (active) { beg = ptr[node]; end = ptr[node + 1]; }

    float acc[8] = {};
    int k = beg;
    for (; k + 4 <= end; k += 4) {
        uint4 u[4];
#pragma unroll
        for (int j = 0; j < 4; j++) u[j] = HW128[csr[k + j] * 8 + sub];
#pragma unroll
        for (int j = 0; j < 4; j++) {
            float2 p0 = h22f2(u[j].x), p1 = h22f2(u[j].y);
            float2 p2 = h22f2(u[j].z), p3 = h22f2(u[j].w);
            acc[0] += p0.x; acc[1] += p0.y; acc[2] += p1.x; acc[3] += p1.y;
            acc[4] += p2.x; acc[5] += p2.y; acc[6] += p3.x; acc[7] += p3.y;
        }
    }
    for (; k < end; k++) {
        uint4 u = HW128[csr[k] * 8 + sub];
        float2 p0 = h22f2(u.x), p1 = h22f2(u.y);
        float2 p2 = h22f2(u.z), p3 = h22f2(u.w);
        acc[0] += p0.x; acc[1] += p0.y; acc[2] += p1.x; acc[3] += p1.y;
        acc[4] += p2.x; acc[5] += p2.y; acc[6] += p3.x; acc[7] += p3.y;
    }

    float dd = active ? g_dinv[g * NND + node] : 0.0f;
    float4 bv0 = ((const float4*)bias)[sub * 2];
    float4 bv1 = ((const float4*)bias)[sub * 2 + 1];
    F8 o;
    o.v[0] = acc[0] * dd + bv0.x; o.v[1] = acc[1] * dd + bv0.y;
    o.v[2] = acc[2] * dd + bv0.z; o.v[3] = acc[3] * dd + bv0.w;
    o.v[4] = acc[4] * dd + bv1.x; o.v[5] = acc[5] * dd + bv1.y;
    o.v[6] = acc[6] * dd + bv1.z; o.v[7] = acc[7] * dd + bv1.w;
    float ss = 0.f;
#pragma unroll
    for (int i = 0; i < 8; i++) ss += o.v[i] * o.v[i];
    ss = hsum8(ss);
    float inv = 1.0f / fmaxf(sqrtf(ss), 1e-12f);
#pragma unroll
    for (int i = 0; i < 8; i++) o.v[i] *= inv;
    return o;
}

__device__ __forceinline__ uint4 f8h8(const F8& h) {
    uint4 r;
    r.x = f2h2(make_float2(h.v[0], h.v[1]));
    r.y = f2h2(make_float2(h.v[2], h.v[3]));
    r.z = f2h2(make_float2(h.v[4], h.v[5]));
    r.w = f2h2(make_float2(h.v[6], h.v[7]));
    return r;
}

/* global gather: 4 nodes per warp */
__global__ void gather_k(const float* __restrict__ bias, int mode) {
    int t = blockIdx.x * blockDim.x + threadIdx.x;
    int w = t >> 5, lane = t & 31;
    if (w >= NND4) return;
    int sub = lane & 7;
    int node = w * 4 + (lane >> 3);
    bool act = node < NND;
    F8 h = gather_core8(g_hw, 0, 0, bias, node, sub, act);
    if (!act) return;
    int offq = node * 8 + sub;                 /* uint4 / (2xfloat4) index */
    float4 r0 = ((const float4*)g_base)[offq * 2];
    float4 r1 = ((const float4*)g_base)[offq * 2 + 1];
    float sc = (mode == 0) ? 1.0f : 0.5f;
    float4 n0 = make_float4(r0.x + sc * h.v[0], r0.y + sc * h.v[1],
                            r0.z + sc * h.v[2], r0.w + sc * h.v[3]);
    float4 n1 = make_float4(r1.x + sc * h.v[4], r1.y + sc * h.v[5],
                            r1.z + sc * h.v[6], r1.w + sc * h.v[7]);
    ((float4*)g_base)[offq * 2]     = n0;
    ((float4*)g_base)[offq * 2 + 1] = n1;
    if (mode == 0) {
        ((uint4*)g_h16)[offq] = f8h8(h);
    } else {
        F8 nb;
        nb.v[0] = n0.x; nb.v[1] = n0.y; nb.v[2] = n0.z; nb.v[3] = n0.w;
        nb.v[4] = n1.x; nb.v[5] = n1.y; nb.v[6] = n1.z; nb.v[7] = n1.w;
        ((uint4*)g_b16)[offq] = f8h8(nb);
    }
}

/* behavioral layer 0 gather: 4 nodes per warp, 3 behaviors */
__global__ void gather3_k(const float* __restrict__ bb) {
    int t = blockIdx.x * blockDim.x + threadIdx.x;
    int w = t >> 5, lane = t & 31;
    if (w >= 3 * NND4) return;
    int b = w / NND4, i = w - b * NND4;
    int sub = lane & 7;
    int node = i * 4 + (lane >> 3);
    bool act = node < NND;
    F8 h = gather_core8(g_hwb[b], E_GLOBAL + b * E_BEH, 1 + b,
                        bb + (b * 2) * 64, node, sub, act);
    if (!act) return;
    int offq = node * 8 + sub;
    ((uint4*)g_hb16[b])[offq] = f8h8(h);
    float4 r0 = ((const float4*)g_base)[offq * 2];
    float4 r1 = ((const float4*)g_base)[offq * 2 + 1];
    F8 res;
    res.v[0] = r0.x + h.v[0]; res.v[1] = r0.y + h.v[1];
    res.v[2] = r0.z + h.v[2]; res.v[3] = r0.w + h.v[3];
    res.v[4] = r1.x + h.v[4]; res.v[5] = r1.y + h.v[5];
    res.v[6] = r1.z + h.v[6]; res.v[7] = r1.w + h.v[7];
    ((uint4*)g_beh16[b])[offq] = f8h8(res);
}

/* behavioral layer 1 gather + attention + combine — marked nodes, 4/warp */
__global__ void gather3attn_k(const float* __restrict__ bb) {
    int t = blockIdx.x * blockDim.x + threadIdx.x;
    int w = t >> 5, lane = t & 31;
    if (w >= NND4) return;
    int sub = lane & 7;
    int node = w * 4 + (lane >> 3);
    bool act = (node < NND) && (g_mark[node] != 0);
    if (__ballot_sync(0xffffffffu, act) == 0u) return;
    int offq = node * 8 + sub;

    F8 tok[3];
#pragma unroll
    for (int b = 0; b < 3; b++) {
        F8 h = gather_core8(g_hwb[b], E_GLOBAL + b * E_BEH, 1 + b,
                            bb + (b * 2 + 1) * 64, node, sub, act);
        F8 r = {};
        if (act) {
            uint4 u = ((const uint4*)g_beh16[b])[offq];
            float2 p0 = h22f2(u.x), p1 = h22f2(u.y);
            float2 p2 = h22f2(u.z), p3 = h22f2(u.w);
            r.v[0] = p0.x; r.v[1] = p0.y; r.v[2] = p1.x; r.v[3] = p1.y;
            r.v[4] = p2.x; r.v[5] = p2.y; r.v[6] = p3.x; r.v[7] = p3.y;
        }
#pragma unroll
        for (int i = 0; i < 8; i++) tok[b].v[i] = r.v[i] + 0.5f * h.v[i];
    }

    float d00 = 0.f, d01 = 0.f, d02 = 0.f, d11 = 0.f, d12 = 0.f, d22 = 0.f;
#pragma unroll
    for (int i = 0; i < 8; i++) {
        d00 += tok[0].v[i] * tok[0].v[i];
        d01 += tok[0].v[i] * tok[1].v[i];
        d02 += tok[0].v[i] * tok[2].v[i];
        d11 += tok[1].v[i] * tok[1].v[i];
        d12 += tok[1].v[i] * tok[2].v[i];
        d22 += tok[2].v[i] * tok[2].v[i];
    }
    float s00 = hsum8(d00), s01 = hsum8(d01), s02 = hsum8(d02);
    float s11 = hsum8(d11), s12 = hsum8(d12), s22 = hsum8(d22);

    if (!act) return;

    const float sc = 0.125f;
    float s[3][3] = {{s00 * sc, s01 * sc, s02 * sc},
                     {s01 * sc, s11 * sc, s12 * sc},
                     {s02 * sc, s12 * sc, s22 * sc}};

    bool isU = node < NU;
    float gw = isU ? 2.35f : 1.0f;
    float bw = isU ? 0.242f : 0.55f;
    float4 gv0 = ((const float4*)g_base)[offq * 2];
    float4 gv1 = ((const float4*)g_base)[offq * 2 + 1];
    float gvv[8] = {gv0.x, gv0.y, gv0.z, gv0.w, gv1.x, gv1.y, gv1.z, gv1.w};

#pragma unroll
    for (int b = 0; b < 3; b++) {
        float m  = fmaxf(s[b][0], fmaxf(s[b][1], s[b][2]));
        float e0 = __expf(s[b][0] - m), e1 = __expf(s[b][1] - m), e2 = __expf(s[b][2] - m);
        float is = 1.0f / (e0 + e1 + e2);
        float a0 = e0 * is, a1 = e1 * is, a2 = e2 * is;
        float o[8];
#pragma unroll
        for (int i = 0; i < 8; i++)
            o[i] = gw * gvv[i] + bw * (a0 * tok[0].v[i] + a1 * tok[1].v[i] + a2 * tok[2].v[i]);
        ((float4*)g_w[b])[offq * 2]     = make_float4(o[0], o[1], o[2], o[3]);
        ((float4*)g_w[b])[offq * 2 + 1] = make_float4(o[4], o[5], o[6], o[7]);
    }
}

/* ---------------- BPR loss ---------------- */
__global__ void loss_k(const int* __restrict__ bd, float* out) {
    int t = blockIdx.x * blockDim.x + threadIdx.x;
    int w = t >> 5, lane = t & 31;
    float partial = 0.0f;
    if (w < BATCH * 9) {
        int k = w / 9, pr = w - k * 9;
        int i = pr / 3, j = pr - i * 3;
        int u   = bd[k * 9 + i * 3 + 0];
        int ip  = bd[k * 9 + i * 3 + 1];
        int in_ = bd[k * 9 + i * 3 + 2];
        float2 uu = ((const float2*)g_w[i])[u * 32 + lane];
        float2 pp = ((const float2*)g_w[j])[(NU + ip) * 32 + lane];
        float2 nn = ((const float2*)g_w[j])[(NU + in_) * 32 + lane];
        float sp = warp_sum(uu.x * pp.x + uu.y * pp.y);
        float sn = warp_sum(uu.x * nn.x + uu.y * nn.y);
        float x  = sp - sn;
        float ls = fminf(x, 0.0f) - log1pf(expf(-fabsf(x)));
        partial = -ls * (1.0f / (float)BATCH);
    }
    __shared__ float sm[8];
    if (lane == 0) sm[threadIdx.x >> 5] = partial;
    __syncthreads();
    if (threadIdx.x == 0) {
        float s = 0.0f;
#pragma unroll
        for (int q = 0; q < 8; q++) s += sm[q];
        atomicAdd(out, s);
    }
}

__global__ void final_k(float* out) {
    out[0] += 0.001f * ((sqrtf(g_sc[0]) + sqrtf(g_sc[1])) / (float)(N_ITEMS + 1));
}

/* ================================ launch ================================ */
extern "C" void kernel_launch(void* const* d_in, const int* in_sizes, int n_in,
                              void* d_out, int out_size) {
    const float* ue  = (const float*)d_in[0];
    const float* ie  = (const float*)d_in[1];
    const float* gW  = (const float*)d_in[2];
    const float* gb  = (const float*)d_in[3];
    const float* bW  = (const float*)d_in[4];
    const float* bb  = (const float*)d_in[5];
    const int*   aei = (const int*)d_in[6];
    const int*   bei = (const int*)d_in[7];
    const int*   bd  = (const int*)d_in[8];
    float* out = (float*)d_out;

    const int T = 256;
    dim3 blk(T);

    zero0_k<<<1, 32>>>(out);
    concat_k<<<(NND * 16 + T - 1) / T, blk>>>(ue, ie);
    mark_k<<<(BATCH * 9 + T - 1) / T, blk>>>(bd);

    degcnt_all_k<<<(E_TOT / 8 + T - 1) / T, blk>>>(aei, bei);

    part_k<<<4 * NCH, SCB>>>();
    scanpart_k<<<1, 256>>>();
    scan_k<<<4 * NCH, SCB>>>();
    fill_all_k<<<(E_TOT / 8 + T - 1) / T, blk>>>(aei, bei);

    const int GEMM_BLOCKS = (NND + 127) / 128;
    const int GW_BLOCKS   = (NND4 * 32 + T - 1) / T;       /* 4 nodes/warp */
    const int GW3_BLOCKS  = (3 * NND4 * 32 + T - 1) / T;

    /* global encoder: 2 layers */
    gemm_k<<<GEMM_BLOCKS, 256>>>(gW, 0);
    gather_k<<<GW_BLOCKS, blk>>>(gb, 0);
    gemm_k<<<GEMM_BLOCKS, 256>>>(gW + 4096, 1);
    gather_k<<<GW_BLOCKS, blk>>>(gb + 64, 1);

    /* behavioral encoders */
    dim3 g3(GEMM_BLOCKS, 3);
    gemm3_k<<<g3, 256>>>(bW, 0);
    gather3_k<<<GW3_BLOCKS, blk>>>(bb);
    gemm3_k<<<g3, 256>>>(bW, 1);
    gather3attn_k<<<GW_BLOCKS, blk>>>(bb);

    loss_k<<<(BATCH * 9 * 32 + T - 1) / T, blk>>>(bd, out);
    final_k<<<1, 1>>>(out);
}

// round 13
// speedup vs baseline: 1.0615x; 1.0615x over previous
#include <cuda_runtime.h>
#include <cuda_fp16.h>
#include <math.h>
#include <stdint.h>

#define N_USERS 60000
#define N_ITEMS 40000
#define NU      60001
#define NND     100002
#define NND4    ((NND + 3) / 4)
#define D       64
#define ND64    (NND * 64)
#define E_GLOBAL 1000000
#define E_BEH    500000
#define E_TOT   (E_GLOBAL + 3 * E_BEH)
#define BATCH    4096

#define SCB 512
#define NCH ((NND + SCB - 1) / SCB)

/* fused-kernel grid partitions */
#define NB_CONCAT ((NND * 16 + 255) / 256)          /* 6251 */
#define NB_DEG    ((E_TOT / 4 + 255) / 256)         /* 2442 */
#define NB_MARK   ((BATCH * 9 + 255) / 256)         /* 144 */
#define GEMM_BLOCKS ((NND + 127) / 128)             /* 782 */
#define NB_FILL   ((E_TOT / 4 + 255) / 256)         /* 2442 */

/* ---------------- scratch (all node state fp16 except g_w) ---------------- */
__device__ __align__(16) __half g_hw[ND64];       /* global dinv*h@W */
__device__ __align__(16) __half g_hwb[3][ND64];   /* behavioral dinv*h@W */
__device__ __align__(16) __half g_b16[ND64];      /* running base/res (in-place) */
__device__ __align__(16) __half g_h16[ND64];      /* global h */
__device__ __align__(16) __half g_hb16[3][ND64];  /* behavioral h */
__device__ __align__(16) __half g_beh16[3][ND64]; /* behavioral res */
__device__ float  g_w[3][ND64];                   /* combined uw/iw (marked rows) */
__device__ float  g_dinv[4 * NND];
__device__ int    g_deg[4 * NND];
__device__ int    g_part[4 * NCH];
__device__ int    g_ptr[4 * (NND + 1)];
__device__ int    g_cnt[4 * NND];
__device__ int    g_csr[E_TOT];
__device__ int    g_mark[NND];
__device__ float  g_sc[2];

/* ---------------- helpers ---------------- */
__device__ __forceinline__ float warp_sum(float v) {
#pragma unroll
    for (int o = 16; o; o >>= 1) v += __shfl_xor_sync(0xffffffffu, v, o);
    return v;
}
__device__ __forceinline__ float hsum8(float v) {
#pragma unroll
    for (int o = 4; o; o >>= 1) v += __shfl_xor_sync(0xffffffffu, v, o);
    return v;
}
__device__ __forceinline__ uint32_t f2h2(float2 v) {
    __half2 h = __floats2half2_rn(v.x, v.y);
    return *(uint32_t*)&h;
}
__device__ __forceinline__ float2 h22f2(uint32_t u) {
    return __half22float2(*(__half2*)&u);
}
__device__ __forceinline__ uint2 f4h4(float4 v) {
    return make_uint2(f2h2(make_float2(v.x, v.y)), f2h2(make_float2(v.z, v.w)));
}

__device__ __forceinline__ void mma16816(float4& c, uint32_t a0, uint32_t a1,
                                         uint32_t a2, uint32_t a3,
                                         uint32_t b0, uint32_t b1) {
    asm volatile(
        "mma.sync.aligned.m16n8k16.row.col.f32.f16.f16.f32 "
        "{%0,%1,%2,%3}, {%4,%5,%6,%7}, {%8,%9}, {%0,%1,%2,%3};"
        : "+f"(c.x), "+f"(c.y), "+f"(c.z), "+f"(c.w)
        : "r"(a0), "r"(a1), "r"(a2), "r"(a3), "r"(b0), "r"(b1));
}

/* ---------------- zero: g_deg, g_mark, g_sc, out ---------------- */
__global__ void zero_k(float* out) {
    int i = blockIdx.x * blockDim.x + threadIdx.x;
    if (i < 4 * NND) g_deg[i] = 0;
    if (i < NND) g_mark[i] = 0;
    if (i < 2) g_sc[i] = 0.0f;
    if (i == 2) out[0] = 0.0f;
}

/* ====== FUSED: concat+sumsq | degcnt (4/thr) | mark ====== */
__global__ __launch_bounds__(256) void init_fused_k(
    const float* __restrict__ ue, const float* __restrict__ ie,
    const int* __restrict__ aei, const int* __restrict__ bei,
    const int* __restrict__ bd) {
    int blk = blockIdx.x;
    if (blk < NB_CONCAT) {
        int t = blk * 256 + threadIdx.x;
        float su = 0.0f, si = 0.0f;
        if (t < NND * 16) {
            int node = t >> 4, q = t & 15;
            float4 v;
            if (node < NU) {
                v = ((const float4*)ue)[node * 16 + q];
                su = v.x * v.x + v.y * v.y + v.z * v.z + v.w * v.w;
            } else {
                v = ((const float4*)ie)[(node - NU) * 16 + q];
                si = v.x * v.x + v.y * v.y + v.z * v.z + v.w * v.w;
            }
            ((uint2*)g_b16)[t] = f4h4(v);
        }
        su = warp_sum(su);
        si = warp_sum(si);
        __shared__ float smu[8], smi[8];
        int w = threadIdx.x >> 5, l = threadIdx.x & 31;
        if (l == 0) { smu[w] = su; smi[w] = si; }
        __syncthreads();
        if (threadIdx.x == 0) {
            float a = 0.f, b = 0.f;
#pragma unroll
            for (int q = 0; q < 8; q++) { a += smu[q]; b += smi[q]; }
            if (a != 0.f) atomicAdd(&g_sc[0], a);
            if (b != 0.f) atomicAdd(&g_sc[1], b);
        }
    } else if (blk < NB_CONCAT + NB_DEG) {
        int q = (blk - NB_CONCAT) * 256 + threadIdx.x;
        if (q >= E_TOT / 4) return;
        int4 d4;
        int g;
        if (q < E_GLOBAL / 4) {
            g = 0;
            d4 = ((const int4*)(aei + E_GLOBAL))[q];
        } else {
            int r = q - E_GLOBAL / 4;
            int b = r / (E_BEH / 4), o = r - b * (E_BEH / 4);
            g = 1 + b;
            d4 = ((const int4*)(bei + (b * 2 + 1) * E_BEH))[o];
        }
        int* deg = g_deg + g * NND;
        atomicAdd(&deg[d4.x], 1);
        atomicAdd(&deg[d4.y], 1);
        atomicAdd(&deg[d4.z], 1);
        atomicAdd(&deg[d4.w], 1);
    } else {
        int t = (blk - NB_CONCAT - NB_DEG) * 256 + threadIdx.x;
        if (t >= BATCH * 9) return;
        int k = t / 9, r = t - k * 9;
        int i = r / 3, c = r - i * 3;
        int val = bd[k * 9 + i * 3 + c];
        if (c == 0) g_mark[val] = 1;
        else        g_mark[NU + val] = 1;
    }
}

/* ---------------- CSR build ---------------- */
__global__ __launch_bounds__(SCB) void part_k() {
    __shared__ int sm[SCB];
    int b = blockIdx.x;
    int g = b / NCH, ch = b % NCH;
    int idx = ch * SCB + threadIdx.x;
    int v = (idx < NND) ? g_deg[g * NND + idx] : 0;
    sm[threadIdx.x] = v;
    __syncthreads();
    for (int o = SCB / 2; o; o >>= 1) {
        if (threadIdx.x < o) sm[threadIdx.x] += sm[threadIdx.x + o];
        __syncthreads();
    }
    if (threadIdx.x == 0) g_part[b] = sm[0];
}

__global__ __launch_bounds__(256) void scanpart_k() {
    __shared__ int sm[256];
    for (int g = 0; g < 4; g++) {
        int v = (threadIdx.x < NCH) ? g_part[g * NCH + threadIdx.x] : 0;
        sm[threadIdx.x] = v;
        __syncthreads();
        for (int o = 1; o < 256; o <<= 1) {
            int a = (threadIdx.x >= o) ? sm[threadIdx.x - o] : 0;
            __syncthreads();
            sm[threadIdx.x] += a;
            __syncthreads();
        }
        if (threadIdx.x < NCH) g_part[g * NCH + threadIdx.x] = sm[threadIdx.x] - v;
        if (threadIdx.x == NCH - 1) g_ptr[g * (NND + 1) + NND] = sm[threadIdx.x];
        __syncthreads();
    }
}

/* scan + fused dinv */
__global__ __launch_bounds__(SCB) void scan_k() {
    __shared__ int sm[SCB];
    int b = blockIdx.x;
    int g = b / NCH, ch = b % NCH;
    int idx = ch * SCB + threadIdx.x;
    int v = (idx < NND) ? g_deg[g * NND + idx] : 0;
    sm[threadIdx.x] = v;
    __syncthreads();
    for (int o = 1; o < SCB; o <<= 1) {
        int add = (threadIdx.x >= o) ? sm[threadIdx.x - o] : 0;
        __syncthreads();
        sm[threadIdx.x] += add;
        __syncthreads();
    }
    int excl = sm[threadIdx.x] - v + g_part[b];
    if (idx < NND) {
        g_ptr[g * (NND + 1) + idx] = excl;
        g_cnt[g * NND + idx]       = excl;
        g_dinv[g * NND + idx]      = (v > 0) ? rsqrtf((float)v) : 0.0f;
    }
}

/* --------- HMMA GEMM body: HW = fp16(dinv * (A16 @ W)), 128 rows/CTA --------- */
#define SAS 72
__device__ __forceinline__ void gemm_body(const __half* __restrict__ A16,
                                          const float* __restrict__ W,
                                          __half* __restrict__ HW, int row0,
                                          const float* __restrict__ dv) {
    __shared__ __half sA[128 * SAS];
    __shared__ __half sWt[64 * SAS];
    int tid = threadIdx.x;

#pragma unroll
    for (int i = 0; i < 4; i++) {
        int idx = tid + i * 256;
        int r = idx >> 3, c8 = idx & 7;
        uint4 u = make_uint4(0u, 0u, 0u, 0u);
        int row = row0 + r;
        if (row < NND) u = ((const uint4*)A16)[row * 8 + c8];
        *(uint4*)(sA + r * SAS + c8 * 8) = u;
    }
#pragma unroll
    for (int i = 0; i < 4; i++) {
        int idx = tid + i * 256;
        int k = idx >> 4, n4 = (idx & 15) * 4;
        float4 w = ((const float4*)W)[idx];
        sWt[(n4 + 0) * SAS + k] = __float2half_rn(w.x);
        sWt[(n4 + 1) * SAS + k] = __float2half_rn(w.y);
        sWt[(n4 + 2) * SAS + k] = __float2half_rn(w.z);
        sWt[(n4 + 3) * SAS + k] = __float2half_rn(w.w);
    }
    __syncthreads();

    int wid = tid >> 5, lane = tid & 31;
    int gq = lane >> 2, tg = lane & 3;
    int mrow = wid * 16;

    float4 acc[8];
#pragma unroll
    for (int n = 0; n < 8; n++) acc[n] = make_float4(0.f, 0.f, 0.f, 0.f);

#pragma unroll
    for (int ks = 0; ks < 4; ks++) {
        int k0 = ks * 16 + tg * 2;
        uint32_t a0 = *(uint32_t*)(sA + (mrow + gq) * SAS + k0);
        uint32_t a1 = *(uint32_t*)(sA + (mrow + gq + 8) * SAS + k0);
        uint32_t a2 = *(uint32_t*)(sA + (mrow + gq) * SAS + k0 + 8);
        uint32_t a3 = *(uint32_t*)(sA + (mrow + gq + 8) * SAS + k0 + 8);
#pragma unroll
        for (int n = 0; n < 8; n++) {
            uint32_t b0 = *(uint32_t*)(sWt + (n * 8 + gq) * SAS + k0);
            uint32_t b1 = *(uint32_t*)(sWt + (n * 8 + gq) * SAS + k0 + 8);
            mma16816(acc[n], a0, a1, a2, a3, b0, b1);
        }
    }

    int r0 = row0 + mrow + gq;
    int r1 = r0 + 8;
    float s0 = (r0 < NND) ? dv[r0] : 0.0f;
    float s1 = (r1 < NND) ? dv[r1] : 0.0f;
#pragma unroll
    for (int n = 0; n < 8; n++) {
        int col = n * 8 + tg * 2;
        if (r0 < NND)
            *(uint32_t*)(HW + r0 * 64 + col) = f2h2(make_float2(acc[n].x * s0, acc[n].y * s0));
        if (r1 < NND)
            *(uint32_t*)(HW + r1 * 64 + col) = f2h2(make_float2(acc[n].z * s1, acc[n].w * s1));
    }
}

/* ====== FUSED: global layer-1 GEMM | fill (4/thr) ====== */
__global__ __launch_bounds__(256) void fill_gemm_k(
    const int* __restrict__ aei, const int* __restrict__ bei,
    const float* __restrict__ gW) {
    if (blockIdx.x < GEMM_BLOCKS) {
        gemm_body(g_b16, gW, g_hw, blockIdx.x * 128, g_dinv);
        return;
    }
    int q = (blockIdx.x - GEMM_BLOCKS) * 256 + threadIdx.x;
    if (q >= E_TOT / 4) return;
    int4 s4, d4;
    int g, base;
    if (q < E_GLOBAL / 4) {
        g = 0;
        base = 0;
        s4 = ((const int4*)aei)[q];
        d4 = ((const int4*)(aei + E_GLOBAL))[q];
    } else {
        int r = q - E_GLOBAL / 4;
        int b = r / (E_BEH / 4), o = r - b * (E_BEH / 4);
        g = 1 + b;
        base = E_GLOBAL + b * E_BEH;
        s4 = ((const int4*)(bei + (b * 2) * E_BEH))[o];
        d4 = ((const int4*)(bei + (b * 2 + 1) * E_BEH))[o];
    }
    int* cnt = g_cnt + g * NND;
    int* csr = g_csr + base;
    csr[atomicAdd(&cnt[d4.x], 1)] = s4.x;
    csr[atomicAdd(&cnt[d4.y], 1)] = s4.y;
    csr[atomicAdd(&cnt[d4.z], 1)] = s4.z;
    csr[atomicAdd(&cnt[d4.w], 1)] = s4.w;
}

__global__ __launch_bounds__(256) void gemm_k(const float* __restrict__ W, int srcsel) {
    gemm_body(srcsel ? g_h16 : g_b16, W, g_hw, blockIdx.x * 128, g_dinv);
}

__global__ __launch_bounds__(256) void gemm3_k(const float* __restrict__ bW, int l) {
    int b = blockIdx.y;
    const __half* A16 = l ? g_hb16[b] : g_b16;
    gemm_body(A16, bW + (b * 2 + l) * 4096, g_hwb[b], blockIdx.x * 128,
              g_dinv + (1 + b) * NND);
}

/* ------- 8-lane gather core: quarter-warp per node, lane owns 8 cols ------- */
struct F8 { float v[8]; };

__device__ __forceinline__ F8 gather_core8(
    const __half* __restrict__ HW, int csr_base, int g,
    const float* __restrict__ bias, int node, int sub, bool active) {

    const int* ptr = g_ptr + g * (NND + 1);
    const int* csr = g_csr + csr_base;
    const uint4* HW128 = (const uint4*)HW;
    int beg = 0, end = 0;
    if (active) { beg = ptr[node]; end = ptr[node + 1]; }

    float acc[8] = {};
    int k = beg;
    for (; k + 4 <= end; k += 4) {
        uint4 u[4];
#pragma unroll
        for (int j = 0; j < 4; j++) u[j] = HW128[csr[k + j] * 8 + sub];
#pragma unroll
        for (int j = 0; j < 4; j++) {
            float2 p0 = h22f2(u[j].x), p1 = h22f2(u[j].y);
            float2 p2 = h22f2(u[j].z), p3 = h22f2(u[j].w);
            acc[0] += p0.x; acc[1] += p0.y; acc[2] += p1.x; acc[3] += p1.y;
            acc[4] += p2.x; acc[5] += p2.y; acc[6] += p3.x; acc[7] += p3.y;
        }
    }
    for (; k < end; k++) {
        uint4 u = HW128[csr[k] * 8 + sub];
        float2 p0 = h22f2(u.x), p1 = h22f2(u.y);
        float2 p2 = h22f2(u.z), p3 = h22f2(u.w);
        acc[0] += p0.x; acc[1] += p0.y; acc[2] += p1.x; acc[3] += p1.y;
        acc[4] += p2.x; acc[5] += p2.y; acc[6] += p3.x; acc[7] += p3.y;
    }

    float dd = active ? g_dinv[g * NND + node] : 0.0f;
    float4 bv0 = ((const float4*)bias)[sub * 2];
    float4 bv1 = ((const float4*)bias)[sub * 2 + 1];
    F8 o;
    o.v[0] = acc[0] * dd + bv0.x; o.v[1] = acc[1] * dd + bv0.y;
    o.v[2] = acc[2] * dd + bv0.z; o.v[3] = acc[3] * dd + bv0.w;
    o.v[4] = acc[4] * dd + bv1.x; o.v[5] = acc[5] * dd + bv1.y;
    o.v[6] = acc[6] * dd + bv1.z; o.v[7] = acc[7] * dd + bv1.w;
    float ss = 0.f;
#pragma unroll
    for (int i = 0; i < 8; i++) ss += o.v[i] * o.v[i];
    ss = hsum8(ss);
    float inv = 1.0f / fmaxf(sqrtf(ss), 1e-12f);
#pragma unroll
    for (int i = 0; i < 8; i++) o.v[i] *= inv;
    return o;
}

__device__ __forceinline__ uint4 f8h8(const F8& h) {
    uint4 r;
    r.x = f2h2(make_float2(h.v[0], h.v[1]));
    r.y = f2h2(make_float2(h.v[2], h.v[3]));
    r.z = f2h2(make_float2(h.v[4], h.v[5]));
    r.w = f2h2(make_float2(h.v[6], h.v[7]));
    return r;
}
__device__ __forceinline__ F8 h8f8(uint4 u) {
    F8 r;
    float2 p0 = h22f2(u.x), p1 = h22f2(u.y);
    float2 p2 = h22f2(u.z), p3 = h22f2(u.w);
    r.v[0] = p0.x; r.v[1] = p0.y; r.v[2] = p1.x; r.v[3] = p1.y;
    r.v[4] = p2.x; r.v[5] = p2.y; r.v[6] = p3.x; r.v[7] = p3.y;
    return r;
}

/* global gather: 4 nodes/warp; base kept fp16 in g_b16 (in-place update) */
__global__ void gather_k(const float* __restrict__ bias, int mode) {
    int t = blockIdx.x * blockDim.x + threadIdx.x;
    int w = t >> 5, lane = t & 31;
    if (w >= NND4) return;
    int sub = lane & 7;
    int node = w * 4 + (lane >> 3);
    bool act = node < NND;
    F8 h = gather_core8(g_hw, 0, 0, bias, node, sub, act);
    if (!act) return;
    int offq = node * 8 + sub;
    F8 r = h8f8(((const uint4*)g_b16)[offq]);
    float sc = (mode == 0) ? 1.0f : 0.5f;
    F8 nb;
#pragma unroll
    for (int i = 0; i < 8; i++) nb.v[i] = r.v[i] + sc * h.v[i];
    ((uint4*)g_b16)[offq] = f8h8(nb);
    if (mode == 0) ((uint4*)g_h16)[offq] = f8h8(h);
}

/* behavioral layer 0 gather: 4 nodes/warp, 3 behaviors */
__global__ void gather3_k(const float* __restrict__ bb) {
    int t = blockIdx.x * blockDim.x + threadIdx.x;
    int w = t >> 5, lane = t & 31;
    if (w >= 3 * NND4) return;
    int b = w / NND4, i = w - b * NND4;
    int sub = lane & 7;
    int node = i * 4 + (lane >> 3);
    bool act = node < NND;
    F8 h = gather_core8(g_hwb[b], E_GLOBAL + b * E_BEH, 1 + b,
                        bb + (b * 2) * 64, node, sub, act);
    if (!act) return;
    int offq = node * 8 + sub;
    ((uint4*)g_hb16[b])[offq] = f8h8(h);
    F8 r = h8f8(((const uint4*)g_b16)[offq]);
    F8 res;
#pragma unroll
    for (int j = 0; j < 8; j++) res.v[j] = r.v[j] + h.v[j];
    ((uint4*)g_beh16[b])[offq] = f8h8(res);
}

/* behavioral layer 1 gather + attention + combine — marked nodes, 4/warp */
__global__ void gather3attn_k(const float* __restrict__ bb) {
    int t = blockIdx.x * blockDim.x + threadIdx.x;
    int w = t >> 5, lane = t & 31;
    if (w >= NND4) return;
    int sub = lane & 7;
    int node = w * 4 + (lane >> 3);
    bool act = (node < NND) && (g_mark[node] != 0);
    if (__ballot_sync(0xffffffffu, act) == 0u) return;
    int offq = node * 8 + sub;

    F8 tok[3];
#pragma unroll
    for (int b = 0; b < 3; b++) {
        F8 h = gather_core8(g_hwb[b], E_GLOBAL + b * E_BEH, 1 + b,
                            bb + (b * 2 + 1) * 64, node, sub, act);
        F8 r = {};
        if (act) r = h8f8(((const uint4*)g_beh16[b])[offq]);
#pragma unroll
        for (int i = 0; i < 8; i++) tok[b].v[i] = r.v[i] + 0.5f * h.v[i];
    }

    float d00 = 0.f, d01 = 0.f, d02 = 0.f, d11 = 0.f, d12 = 0.f, d22 = 0.f;
#pragma unroll
    for (int i = 0; i < 8; i++) {
        d00 += tok[0].v[i] * tok[0].v[i];
        d01 += tok[0].v[i] * tok[1].v[i];
        d02 += tok[0].v[i] * tok[2].v[i];
        d11 += tok[1].v[i] * tok[1].v[i];
        d12 += tok[1].v[i] * tok[2].v[i];
        d22 += tok[2].v[i] * tok[2].v[i];
    }
    float s00 = hsum8(d00), s01 = hsum8(d01), s02 = hsum8(d02);
    float s11 = hsum8(d11), s12 = hsum8(d12), s22 = hsum8(d22);

    if (!act) return;

    const float sc = 0.125f;
    float s[3][3] = {{s00 * sc, s01 * sc, s02 * sc},
                     {s01 * sc, s11 * sc, s12 * sc},
                     {s02 * sc, s12 * sc, s22 * sc}};

    bool isU = node < NU;
    float gw = isU ? 2.35f : 1.0f;
    float bw = isU ? 0.242f : 0.55f;
    F8 gvv = h8f8(((const uint4*)g_b16)[offq]);

#pragma unroll
    for (int b = 0; b < 3; b++) {
        float m  = fmaxf(s[b][0], fmaxf(s[b][1], s[b][2]));
        float e0 = __expf(s[b][0] - m), e1 = __expf(s[b][1] - m), e2 = __expf(s[b][2] - m);
        float is = 1.0f / (e0 + e1 + e2);
        float a0 = e0 * is, a1 = e1 * is, a2 = e2 * is;
        float o[8];
#pragma unroll
        for (int i = 0; i < 8; i++)
            o[i] = gw * gvv.v[i] + bw * (a0 * tok[0].v[i] + a1 * tok[1].v[i] + a2 * tok[2].v[i]);
        ((float4*)g_w[b])[offq * 2]     = make_float4(o[0], o[1], o[2], o[3]);
        ((float4*)g_w[b])[offq * 2 + 1] = make_float4(o[4], o[5], o[6], o[7]);
    }
}

/* ---------------- BPR loss ---------------- */
__global__ void loss_k(const int* __restrict__ bd, float* out) {
    int t = blockIdx.x * blockDim.x + threadIdx.x;
    int w = t >> 5, lane = t & 31;
    float partial = 0.0f;
    if (w < BATCH * 9) {
        int k = w / 9, pr = w - k * 9;
        int i = pr / 3, j = pr - i * 3;
        int u   = bd[k * 9 + i * 3 + 0];
        int ip  = bd[k * 9 + i * 3 + 1];
        int in_ = bd[k * 9 + i * 3 + 2];
        float2 uu = ((const float2*)g_w[i])[u * 32 + lane];
        float2 pp = ((const float2*)g_w[j])[(NU + ip) * 32 + lane];
        float2 nn = ((const float2*)g_w[j])[(NU + in_) * 32 + lane];
        float sp = warp_sum(uu.x * pp.x + uu.y * pp.y);
        float sn = warp_sum(uu.x * nn.x + uu.y * nn.y);
        float x  = sp - sn;
        float ls = fminf(x, 0.0f) - log1pf(expf(-fabsf(x)));
        partial = -ls * (1.0f / (float)BATCH);
    }
    __shared__ float sm[8];
    if (lane == 0) sm[threadIdx.x >> 5] = partial;
    __syncthreads();
    if (threadIdx.x == 0) {
        float s = 0.0f;
#pragma unroll
        for (int q = 0; q < 8; q++) s += sm[q];
        atomicAdd(out, s);
    }
}

__global__ void final_k(float* out) {
    out[0] += 0.001f * ((sqrtf(g_sc[0]) + sqrtf(g_sc[1])) / (float)(N_ITEMS + 1));
}

/* ================================ launch ================================ */
extern "C" void kernel_launch(void* const* d_in, const int* in_sizes, int n_in,
                              void* d_out, int out_size) {
    const float* ue  = (const float*)d_in[0];
    const float* ie  = (const float*)d_in[1];
    const float* gW  = (const float*)d_in[2];
    const float* gb  = (const float*)d_in[3];
    const float* bW  = (const float*)d_in[4];
    const float* bb  = (const float*)d_in[5];
    const int*   aei = (const int*)d_in[6];
    const int*   bei = (const int*)d_in[7];
    const int*   bd  = (const int*)d_in[8];
    float* out = (float*)d_out;

    const int T = 256;
    dim3 blk(T);

    zero_k<<<(4 * NND + T - 1) / T, blk>>>(out);
    init_fused_k<<<NB_CONCAT + NB_DEG + NB_MARK, blk>>>(ue, ie, aei, bei, bd);

    part_k<<<4 * NCH, SCB>>>();
    scanpart_k<<<1, 256>>>();
    scan_k<<<4 * NCH, SCB>>>();

    /* fill CSR overlapped with the first global GEMM */
    fill_gemm_k<<<GEMM_BLOCKS + NB_FILL, blk>>>(aei, bei, gW);

    const int GW_BLOCKS  = (NND4 * 32 + T - 1) / T;
    const int GW3_BLOCKS = (3 * NND4 * 32 + T - 1) / T;

    gather_k<<<GW_BLOCKS, blk>>>(gb, 0);
    gemm_k<<<GEMM_BLOCKS, 256>>>(gW + 4096, 1);
    gather_k<<<GW_BLOCKS, blk>>>(gb + 64, 1);

    dim3 g3(GEMM_BLOCKS, 3);
    gemm3_k<<<g3, 256>>>(bW, 0);
    gather3_k<<<GW3_BLOCKS, blk>>>(bb);
    gemm3_k<<<g3, 256>>>(bW, 1);
    gather3attn_k<<<GW_BLOCKS, blk>>>(bb);

    loss_k<<<(BATCH * 9 * 32 + T - 1) / T, blk>>>(bd, out);
    final_k<<<1, 1>>>(out);
}

// round 14
// speedup vs baseline: 1.0705x; 1.0085x over previous
#include <cuda_runtime.h>
#include <cuda_fp16.h>
#include <math.h>
#include <stdint.h>

#define N_USERS 60000
#define N_ITEMS 40000
#define NU      60001
#define NND     100002
#define NND4    ((NND + 3) / 4)
#define D       64
#define ND64    (NND * 64)
#define E_GLOBAL 1000000
#define E_BEH    500000
#define E_TOT   (E_GLOBAL + 3 * E_BEH)
#define BATCH    4096

#define SCB 512
#define NCH ((NND + SCB - 1) / SCB)

/* fused-kernel grid partitions */
#define NB_CONCAT ((NND * 16 + 255) / 256)
#define NB_DEG    ((E_TOT / 4 + 255) / 256)
#define NB_MARK   ((BATCH * 9 + 255) / 256)
#define GEMM_BLOCKS ((NND + 127) / 128)
#define NB_FILL   ((E_TOT / 4 + 255) / 256)

/* ------- scratch. INVARIANT: g_deg, g_mark, g_sc are zero at entry of every
   kernel_launch execution and are restored to zero by their last readers. ------- */
__device__ __align__(16) __half g_hw[ND64];
__device__ __align__(16) __half g_hwb[3][ND64];
__device__ __align__(16) __half g_b16[ND64];
__device__ __align__(16) __half g_h16[ND64];
__device__ __align__(16) __half g_hb16[3][ND64];
__device__ __align__(16) __half g_beh16[3][ND64];
__device__ float  g_w[3][ND64];
__device__ float  g_dinv[4 * NND];
__device__ int    g_deg[4 * NND];
__device__ int    g_part[4 * NCH];
__device__ int    g_ptr[4 * (NND + 1)];
__device__ int    g_cnt[4 * NND];
__device__ int    g_csr[E_TOT];
__device__ int    g_mark[NND];
__device__ float  g_sc[2];

/* ---------------- helpers ---------------- */
__device__ __forceinline__ float warp_sum(float v) {
#pragma unroll
    for (int o = 16; o; o >>= 1) v += __shfl_xor_sync(0xffffffffu, v, o);
    return v;
}
__device__ __forceinline__ float hsum8(float v) {
#pragma unroll
    for (int o = 4; o; o >>= 1) v += __shfl_xor_sync(0xffffffffu, v, o);
    return v;
}
__device__ __forceinline__ uint32_t f2h2(float2 v) {
    __half2 h = __floats2half2_rn(v.x, v.y);
    return *(uint32_t*)&h;
}
__device__ __forceinline__ float2 h22f2(uint32_t u) {
    return __half22float2(*(__half2*)&u);
}
__device__ __forceinline__ uint2 f4h4(float4 v) {
    return make_uint2(f2h2(make_float2(v.x, v.y)), f2h2(make_float2(v.z, v.w)));
}

__device__ __forceinline__ void mma16816(float4& c, uint32_t a0, uint32_t a1,
                                         uint32_t a2, uint32_t a3,
                                         uint32_t b0, uint32_t b1) {
    asm volatile(
        "mma.sync.aligned.m16n8k16.row.col.f32.f16.f16.f32 "
        "{%0,%1,%2,%3}, {%4,%5,%6,%7}, {%8,%9}, {%0,%1,%2,%3};"
        : "+f"(c.x), "+f"(c.y), "+f"(c.z), "+f"(c.w)
        : "r"(a0), "r"(a1), "r"(a2), "r"(a3), "r"(b0), "r"(b1));
}

/* ====== FUSED: concat+sumsq | degcnt (4/thr) | mark ====== */
__global__ __launch_bounds__(256) void init_fused_k(
    const float* __restrict__ ue, const float* __restrict__ ie,
    const int* __restrict__ aei, const int* __restrict__ bei,
    const int* __restrict__ bd) {
    int blk = blockIdx.x;
    if (blk < NB_CONCAT) {
        int t = blk * 256 + threadIdx.x;
        float su = 0.0f, si = 0.0f;
        if (t < NND * 16) {
            int node = t >> 4, q = t & 15;
            float4 v;
            if (node < NU) {
                v = ((const float4*)ue)[node * 16 + q];
                su = v.x * v.x + v.y * v.y + v.z * v.z + v.w * v.w;
            } else {
                v = ((const float4*)ie)[(node - NU) * 16 + q];
                si = v.x * v.x + v.y * v.y + v.z * v.z + v.w * v.w;
            }
            ((uint2*)g_b16)[t] = f4h4(v);
        }
        su = warp_sum(su);
        si = warp_sum(si);
        __shared__ float smu[8], smi[8];
        int w = threadIdx.x >> 5, l = threadIdx.x & 31;
        if (l == 0) { smu[w] = su; smi[w] = si; }
        __syncthreads();
        if (threadIdx.x == 0) {
            float a = 0.f, b = 0.f;
#pragma unroll
            for (int q = 0; q < 8; q++) { a += smu[q]; b += smi[q]; }
            if (a != 0.f) atomicAdd(&g_sc[0], a);
            if (b != 0.f) atomicAdd(&g_sc[1], b);
        }
    } else if (blk < NB_CONCAT + NB_DEG) {
        int q = (blk - NB_CONCAT) * 256 + threadIdx.x;
        if (q >= E_TOT / 4) return;
        int4 d4;
        int g;
        if (q < E_GLOBAL / 4) {
            g = 0;
            d4 = ((const int4*)(aei + E_GLOBAL))[q];
        } else {
            int r = q - E_GLOBAL / 4;
            int b = r / (E_BEH / 4), o = r - b * (E_BEH / 4);
            g = 1 + b;
            d4 = ((const int4*)(bei + (b * 2 + 1) * E_BEH))[o];
        }
        int* deg = g_deg + g * NND;
        atomicAdd(&deg[d4.x], 1);
        atomicAdd(&deg[d4.y], 1);
        atomicAdd(&deg[d4.z], 1);
        atomicAdd(&deg[d4.w], 1);
    } else {
        int t = (blk - NB_CONCAT - NB_DEG) * 256 + threadIdx.x;
        if (t >= BATCH * 9) return;
        int k = t / 9, r = t - k * 9;
        int i = r / 3, c = r - i * 3;
        int val = bd[k * 9 + i * 3 + c];
        if (c == 0) g_mark[val] = 1;
        else        g_mark[NU + val] = 1;
    }
}

/* ---------------- CSR build ---------------- */
__global__ __launch_bounds__(SCB) void part_k() {
    __shared__ int sm[SCB];
    int b = blockIdx.x;
    int g = b / NCH, ch = b % NCH;
    int idx = ch * SCB + threadIdx.x;
    int v = (idx < NND) ? g_deg[g * NND + idx] : 0;
    sm[threadIdx.x] = v;
    __syncthreads();
    for (int o = SCB / 2; o; o >>= 1) {
        if (threadIdx.x < o) sm[threadIdx.x] += sm[threadIdx.x + o];
        __syncthreads();
    }
    if (threadIdx.x == 0) g_part[b] = sm[0];
}

/* one block per graph; block 0 also zeroes out[0] for this replay */
__global__ __launch_bounds__(256) void scanpart_k(float* out) {
    __shared__ int sm[256];
    int g = blockIdx.x;
    if (g == 0 && threadIdx.x == 0) out[0] = 0.0f;
    int v = (threadIdx.x < NCH) ? g_part[g * NCH + threadIdx.x] : 0;
    sm[threadIdx.x] = v;
    __syncthreads();
    for (int o = 1; o < 256; o <<= 1) {
        int a = (threadIdx.x >= o) ? sm[threadIdx.x - o] : 0;
        __syncthreads();
        sm[threadIdx.x] += a;
        __syncthreads();
    }
    if (threadIdx.x < NCH) g_part[g * NCH + threadIdx.x] = sm[threadIdx.x] - v;
    if (threadIdx.x == NCH - 1) g_ptr[g * (NND + 1) + NND] = sm[threadIdx.x];
}

/* scan + fused dinv; restores g_deg = 0 (last reader) */
__global__ __launch_bounds__(SCB) void scan_k() {
    __shared__ int sm[SCB];
    int b = blockIdx.x;
    int g = b / NCH, ch = b % NCH;
    int idx = ch * SCB + threadIdx.x;
    int v = (idx < NND) ? g_deg[g * NND + idx] : 0;
    sm[threadIdx.x] = v;
    __syncthreads();
    for (int o = 1; o < SCB; o <<= 1) {
        int add = (threadIdx.x >= o) ? sm[threadIdx.x - o] : 0;
        __syncthreads();
        sm[threadIdx.x] += add;
        __syncthreads();
    }
    int excl = sm[threadIdx.x] - v + g_part[b];
    if (idx < NND) {
        g_ptr[g * (NND + 1) + idx] = excl;
        g_cnt[g * NND + idx]       = excl;
        g_dinv[g * NND + idx]      = (v > 0) ? rsqrtf((float)v) : 0.0f;
        g_deg[g * NND + idx]       = 0;   /* restore invariant */
    }
}

/* --------- HMMA GEMM body --------- */
#define SAS 72
__device__ __forceinline__ void gemm_body(const __half* __restrict__ A16,
                                          const float* __restrict__ W,
                                          __half* __restrict__ HW, int row0,
                                          const float* __restrict__ dv) {
    __shared__ __half sA[128 * SAS];
    __shared__ __half sWt[64 * SAS];
    int tid = threadIdx.x;

#pragma unroll
    for (int i = 0; i < 4; i++) {
        int idx = tid + i * 256;
        int r = idx >> 3, c8 = idx & 7;
        uint4 u = make_uint4(0u, 0u, 0u, 0u);
        int row = row0 + r;
        if (row < NND) u = ((const uint4*)A16)[row * 8 + c8];
        *(uint4*)(sA + r * SAS + c8 * 8) = u;
    }
#pragma unroll
    for (int i = 0; i < 4; i++) {
        int idx = tid + i * 256;
        int k = idx >> 4, n4 = (idx & 15) * 4;
        float4 w = ((const float4*)W)[idx];
        sWt[(n4 + 0) * SAS + k] = __float2half_rn(w.x);
        sWt[(n4 + 1) * SAS + k] = __float2half_rn(w.y);
        sWt[(n4 + 2) * SAS + k] = __float2half_rn(w.z);
        sWt[(n4 + 3) * SAS + k] = __float2half_rn(w.w);
    }
    __syncthreads();

    int wid = tid >> 5, lane = tid & 31;
    int gq = lane >> 2, tg = lane & 3;
    int mrow = wid * 16;

    float4 acc[8];
#pragma unroll
    for (int n = 0; n < 8; n++) acc[n] = make_float4(0.f, 0.f, 0.f, 0.f);

#pragma unroll
    for (int ks = 0; ks < 4; ks++) {
        int k0 = ks * 16 + tg * 2;
        uint32_t a0 = *(uint32_t*)(sA + (mrow + gq) * SAS + k0);
        uint32_t a1 = *(uint32_t*)(sA + (mrow + gq + 8) * SAS + k0);
        uint32_t a2 = *(uint32_t*)(sA + (mrow + gq) * SAS + k0 + 8);
        uint32_t a3 = *(uint32_t*)(sA + (mrow + gq + 8) * SAS + k0 + 8);
#pragma unroll
        for (int n = 0; n < 8; n++) {
            uint32_t b0 = *(uint32_t*)(sWt + (n * 8 + gq) * SAS + k0);
            uint32_t b1 = *(uint32_t*)(sWt + (n * 8 + gq) * SAS + k0 + 8);
            mma16816(acc[n], a0, a1, a2, a3, b0, b1);
        }
    }

    int r0 = row0 + mrow + gq;
    int r1 = r0 + 8;
    float s0 = (r0 < NND) ? dv[r0] : 0.0f;
    float s1 = (r1 < NND) ? dv[r1] : 0.0f;
#pragma unroll
    for (int n = 0; n < 8; n++) {
        int col = n * 8 + tg * 2;
        if (r0 < NND)
            *(uint32_t*)(HW + r0 * 64 + col) = f2h2(make_float2(acc[n].x * s0, acc[n].y * s0));
        if (r1 < NND)
            *(uint32_t*)(HW + r1 * 64 + col) = f2h2(make_float2(acc[n].z * s1, acc[n].w * s1));
    }
}

/* ====== FUSED: global layer-1 GEMM | fill (4/thr) ====== */
__global__ __launch_bounds__(256) void fill_gemm_k(
    const int* __restrict__ aei, const int* __restrict__ bei,
    const float* __restrict__ gW) {
    if (blockIdx.x < GEMM_BLOCKS) {
        gemm_body(g_b16, gW, g_hw, blockIdx.x * 128, g_dinv);
        return;
    }
    int q = (blockIdx.x - GEMM_BLOCKS) * 256 + threadIdx.x;
    if (q >= E_TOT / 4) return;
    int4 s4, d4;
    int g, base;
    if (q < E_GLOBAL / 4) {
        g = 0;
        base = 0;
        s4 = ((const int4*)aei)[q];
        d4 = ((const int4*)(aei + E_GLOBAL))[q];
    } else {
        int r = q - E_GLOBAL / 4;
        int b = r / (E_BEH / 4), o = r - b * (E_BEH / 4);
        g = 1 + b;
        base = E_GLOBAL + b * E_BEH;
        s4 = ((const int4*)(bei + (b * 2) * E_BEH))[o];
        d4 = ((const int4*)(bei + (b * 2 + 1) * E_BEH))[o];
    }
    int* cnt = g_cnt + g * NND;
    int* csr = g_csr + base;
    csr[atomicAdd(&cnt[d4.x], 1)] = s4.x;
    csr[atomicAdd(&cnt[d4.y], 1)] = s4.y;
    csr[atomicAdd(&cnt[d4.z], 1)] = s4.z;
    csr[atomicAdd(&cnt[d4.w], 1)] = s4.w;
}

__global__ __launch_bounds__(256) void gemm_k(const float* __restrict__ W, int srcsel) {
    gemm_body(srcsel ? g_h16 : g_b16, W, g_hw, blockIdx.x * 128, g_dinv);
}

__global__ __launch_bounds__(256) void gemm3_k(const float* __restrict__ bW, int l) {
    int b = blockIdx.y;
    const __half* A16 = l ? g_hb16[b] : g_b16;
    gemm_body(A16, bW + (b * 2 + l) * 4096, g_hwb[b], blockIdx.x * 128,
              g_dinv + (1 + b) * NND);
}

/* ------- 8-lane gather core ------- */
struct F8 { float v[8]; };

__device__ __forceinline__ F8 gather_core8(
    const __half* __restrict__ HW, int csr_base, int g,
    const float* __restrict__ bias, int node, int sub, bool active) {

    const int* ptr = g_ptr + g * (NND + 1);
    const int* csr = g_csr + csr_base;
    const uint4* HW128 = (const uint4*)HW;
    int beg = 0, end = 0;
    if (active) { beg = ptr[node]; end = ptr[node + 1]; }

    float acc[8] = {};
    int k = beg;
    for (; k + 4 <= end; k += 4) {
        uint4 u[4];
#pragma unroll
        for (int j = 0; j < 4; j++) u[j] = HW128[csr[k + j] * 8 + sub];
#pragma unroll
        for (int j = 0; j < 4; j++) {
            float2 p0 = h22f2(u[j].x), p1 = h22f2(u[j].y);
            float2 p2 = h22f2(u[j].z), p3 = h22f2(u[j].w);
            acc[0] += p0.x; acc[1] += p0.y; acc[2] += p1.x; acc[3] += p1.y;
            acc[4] += p2.x; acc[5] += p2.y; acc[6] += p3.x; acc[7] += p3.y;
        }
    }
    for (; k < end; k++) {
        uint4 u = HW128[csr[k] * 8 + sub];
        float2 p0 = h22f2(u.x), p1 = h22f2(u.y);
        float2 p2 = h22f2(u.z), p3 = h22f2(u.w);
        acc[0] += p0.x; acc[1] += p0.y; acc[2] += p1.x; acc[3] += p1.y;
        acc[4] += p2.x; acc[5] += p2.y; acc[6] += p3.x; acc[7] += p3.y;
    }

    float dd = active ? g_dinv[g * NND + node] : 0.0f;
    float4 bv0 = ((const float4*)bias)[sub * 2];
    float4 bv1 = ((const float4*)bias)[sub * 2 + 1];
    F8 o;
    o.v[0] = acc[0] * dd + bv0.x; o.v[1] = acc[1] * dd + bv0.y;
    o.v[2] = acc[2] * dd + bv0.z; o.v[3] = acc[3] * dd + bv0.w;
    o.v[4] = acc[4] * dd + bv1.x; o.v[5] = acc[5] * dd + bv1.y;
    o.v[6] = acc[6] * dd + bv1.z; o.v[7] = acc[7] * dd + bv1.w;
    float ss = 0.f;
#pragma unroll
    for (int i = 0; i < 8; i++) ss += o.v[i] * o.v[i];
    ss = hsum8(ss);
    float inv = 1.0f / fmaxf(sqrtf(ss), 1e-12f);
#pragma unroll
    for (int i = 0; i < 8; i++) o.v[i] *= inv;
    return o;
}

__device__ __forceinline__ uint4 f8h8(const F8& h) {
    uint4 r;
    r.x = f2h2(make_float2(h.v[0], h.v[1]));
    r.y = f2h2(make_float2(h.v[2], h.v[3]));
    r.z = f2h2(make_float2(h.v[4], h.v[5]));
    r.w = f2h2(make_float2(h.v[6], h.v[7]));
    return r;
}
__device__ __forceinline__ F8 h8f8(uint4 u) {
    F8 r;
    float2 p0 = h22f2(u.x), p1 = h22f2(u.y);
    float2 p2 = h22f2(u.z), p3 = h22f2(u.w);
    r.v[0] = p0.x; r.v[1] = p0.y; r.v[2] = p1.x; r.v[3] = p1.y;
    r.v[4] = p2.x; r.v[5] = p2.y; r.v[6] = p3.x; r.v[7] = p3.y;
    return r;
}

/* global gather: 4 nodes/warp; base fp16 in-place */
__global__ void gather_k(const float* __restrict__ bias, int mode) {
    int t = blockIdx.x * blockDim.x + threadIdx.x;
    int w = t >> 5, lane = t & 31;
    if (w >= NND4) return;
    int sub = lane & 7;
    int node = w * 4 + (lane >> 3);
    bool act = node < NND;
    F8 h = gather_core8(g_hw, 0, 0, bias, node, sub, act);
    if (!act) return;
    int offq = node * 8 + sub;
    F8 r = h8f8(((const uint4*)g_b16)[offq]);
    float sc = (mode == 0) ? 1.0f : 0.5f;
    F8 nb;
#pragma unroll
    for (int i = 0; i < 8; i++) nb.v[i] = r.v[i] + sc * h.v[i];
    ((uint4*)g_b16)[offq] = f8h8(nb);
    if (mode == 0) ((uint4*)g_h16)[offq] = f8h8(h);
}

/* behavioral layer 0 gather */
__global__ void gather3_k(const float* __restrict__ bb) {
    int t = blockIdx.x * blockDim.x + threadIdx.x;
    int w = t >> 5, lane = t & 31;
    if (w >= 3 * NND4) return;
    int b = w / NND4, i = w - b * NND4;
    int sub = lane & 7;
    int node = i * 4 + (lane >> 3);
    bool act = node < NND;
    F8 h = gather_core8(g_hwb[b], E_GLOBAL + b * E_BEH, 1 + b,
                        bb + (b * 2) * 64, node, sub, act);
    if (!act) return;
    int offq = node * 8 + sub;
    ((uint4*)g_hb16[b])[offq] = f8h8(h);
    F8 r = h8f8(((const uint4*)g_b16)[offq]);
    F8 res;
#pragma unroll
    for (int j = 0; j < 8; j++) res.v[j] = r.v[j] + h.v[j];
    ((uint4*)g_beh16[b])[offq] = f8h8(res);
}

/* behavioral layer 1 gather + attention + combine — marked nodes; unmarks after use */
__global__ void gather3attn_k(const float* __restrict__ bb) {
    int t = blockIdx.x * blockDim.x + threadIdx.x;
    int w = t >> 5, lane = t & 31;
    if (w >= NND4) return;
    int sub = lane & 7;
    int node = w * 4 + (lane >> 3);
    bool act = (node < NND) && (g_mark[node] != 0);
    if (__ballot_sync(0xffffffffu, act) == 0u) return;
    int offq = node * 8 + sub;

    F8 tok[3];
#pragma unroll
    for (int b = 0; b < 3; b++) {
        F8 h = gather_core8(g_hwb[b], E_GLOBAL + b * E_BEH, 1 + b,
                            bb + (b * 2 + 1) * 64, node, sub, act);
        F8 r = {};
        if (act) r = h8f8(((const uint4*)g_beh16[b])[offq]);
#pragma unroll
        for (int i = 0; i < 8; i++) tok[b].v[i] = r.v[i] + 0.5f * h.v[i];
    }

    float d00 = 0.f, d01 = 0.f, d02 = 0.f, d11 = 0.f, d12 = 0.f, d22 = 0.f;
#pragma unroll
    for (int i = 0; i < 8; i++) {
        d00 += tok[0].v[i] * tok[0].v[i];
        d01 += tok[0].v[i] * tok[1].v[i];
        d02 += tok[0].v[i] * tok[2].v[i];
        d11 += tok[1].v[i] * tok[1].v[i];
        d12 += tok[1].v[i] * tok[2].v[i];
        d22 += tok[2].v[i] * tok[2].v[i];
    }
    float s00 = hsum8(d00), s01 = hsum8(d01), s02 = hsum8(d02);
    float s11 = hsum8(d11), s12 = hsum8(d12), s22 = hsum8(d22);

    if (!act) return;

    const float sc = 0.125f;
    float s[3][3] = {{s00 * sc, s01 * sc, s02 * sc},
                     {s01 * sc, s11 * sc, s12 * sc},
                     {s02 * sc, s12 * sc, s22 * sc}};

    bool isU = node < NU;
    float gw = isU ? 2.35f : 1.0f;
    float bw = isU ? 0.242f : 0.55f;
    F8 gvv = h8f8(((const uint4*)g_b16)[offq]);

#pragma unroll
    for (int b = 0; b < 3; b++) {
        float m  = fmaxf(s[b][0], fmaxf(s[b][1], s[b][2]));
        float e0 = __expf(s[b][0] - m), e1 = __expf(s[b][1] - m), e2 = __expf(s[b][2] - m);
        float is = 1.0f / (e0 + e1 + e2);
        float a0 = e0 * is, a1 = e1 * is, a2 = e2 * is;
        float o[8];
#pragma unroll
        for (int i = 0; i < 8; i++)
            o[i] = gw * gvv.v[i] + bw * (a0 * tok[0].v[i] + a1 * tok[1].v[i] + a2 * tok[2].v[i]);
        ((float4*)g_w[b])[offq * 2]     = make_float4(o[0], o[1], o[2], o[3]);
        ((float4*)g_w[b])[offq * 2 + 1] = make_float4(o[4], o[5], o[6], o[7]);
    }
    if (sub == 0) g_mark[node] = 0;   /* restore invariant */
}

/* ---------------- BPR loss + fused regularizer; restores g_sc = 0 ---------------- */
__global__ void loss_k(const int* __restrict__ bd, float* out) {
    int t = blockIdx.x * blockDim.x + threadIdx.x;
    int w = t >> 5, lane = t & 31;
    float partial = 0.0f;
    if (w < BATCH * 9) {
        int k = w / 9, pr = w - k * 9;
        int i = pr / 3, j = pr - i * 3;
        int u   = bd[k * 9 + i * 3 + 0];
        int ip  = bd[k * 9 + i * 3 + 1];
        int in_ = bd[k * 9 + i * 3 + 2];
        float2 uu = ((const float2*)g_w[i])[u * 32 + lane];
        float2 pp = ((const float2*)g_w[j])[(NU + ip) * 32 + lane];
        float2 nn = ((const float2*)g_w[j])[(NU + in_) * 32 + lane];
        float sp = warp_sum(uu.x * pp.x + uu.y * pp.y);
        float sn = warp_sum(uu.x * nn.x + uu.y * nn.y);
        float x  = sp - sn;
        float ls = fminf(x, 0.0f) - log1pf(expf(-fabsf(x)));
        partial = -ls * (1.0f / (float)BATCH);
    }
    __shared__ float sm[8];
    if (lane == 0) sm[threadIdx.x >> 5] = partial;
    __syncthreads();
    if (threadIdx.x == 0) {
        float s = 0.0f;
#pragma unroll
        for (int q = 0; q < 8; q++) s += sm[q];
        if (blockIdx.x == 0) {
            s += 0.001f * ((sqrtf(g_sc[0]) + sqrtf(g_sc[1])) / (float)(N_ITEMS + 1));
            g_sc[0] = 0.0f;   /* restore invariant */
            g_sc[1] = 0.0f;
        }
        atomicAdd(out, s);
    }
}

/* ================================ launch ================================ */
extern "C" void kernel_launch(void* const* d_in, const int* in_sizes, int n_in,
                              void* d_out, int out_size) {
    const float* ue  = (const float*)d_in[0];
    const float* ie  = (const float*)d_in[1];
    const float* gW  = (const float*)d_in[2];
    const float* gb  = (const float*)d_in[3];
    const float* bW  = (const float*)d_in[4];
    const float* bb  = (const float*)d_in[5];
    const int*   aei = (const int*)d_in[6];
    const int*   bei = (const int*)d_in[7];
    const int*   bd  = (const int*)d_in[8];
    float* out = (float*)d_out;

    const int T = 256;
    dim3 blk(T);

    init_fused_k<<<NB_CONCAT + NB_DEG + NB_MARK, blk>>>(ue, ie, aei, bei, bd);

    part_k<<<4 * NCH, SCB>>>();
    scanpart_k<<<4, 256>>>(out);
    scan_k<<<4 * NCH, SCB>>>();

    fill_gemm_k<<<GEMM_BLOCKS + NB_FILL, blk>>>(aei, bei, gW);

    const int GW_BLOCKS  = (NND4 * 32 + T - 1) / T;
    const int GW3_BLOCKS = (3 * NND4 * 32 + T - 1) / T;

    gather_k<<<GW_BLOCKS, blk>>>(gb, 0);
    gemm_k<<<GEMM_BLOCKS, 256>>>(gW + 4096, 1);
    gather_k<<<GW_BLOCKS, blk>>>(gb + 64, 1);

    dim3 g3(GEMM_BLOCKS, 3);
    gemm3_k<<<g3, 256>>>(bW, 0);
    gather3_k<<<GW3_BLOCKS, blk>>>(bb);
    gemm3_k<<<g3, 256>>>(bW, 1);
    gather3attn_k<<<GW_BLOCKS, blk>>>(bb);

    loss_k<<<(BATCH * 9 * 32 + T - 1) / T, blk>>>(bd, out);
}

// round 15
// speedup vs baseline: 1.0852x; 1.0137x over previous
#include <cuda_runtime.h>
#include <cuda_fp16.h>
#include <math.h>
#include <stdint.h>

#define N_USERS 60000
#define N_ITEMS 40000
#define NU      60001
#define NND     100002
#define NND4    ((NND + 3) / 4)
#define D       64
#define ND64    (NND * 64)
#define E_GLOBAL 1000000
#define E_BEH    500000
#define E_TOT   (E_GLOBAL + 3 * E_BEH)
#define BATCH    4096

#define SCB 512
#define NCH ((NND + SCB - 1) / SCB)

#define NB_CONCAT ((NND * 16 + 255) / 256)
#define NB_DEG    ((E_TOT / 4 + 255) / 256)
#define NB_MARK   ((BATCH * 9 + 255) / 256)
#define GEMM_BLOCKS ((NND + 127) / 128)
#define NB_FILL   ((E_TOT / 4 + 255) / 256)

/* ------- scratch. INVARIANT: g_deg, g_mark, g_sc zero at entry; restored. ------- */
__device__ __align__(16) __half g_hw[ND64];
__device__ __align__(16) __half g_hwb[3][ND64];
__device__ __align__(16) __half g_b16[ND64];
__device__ __align__(16) __half g_h16[ND64];
__device__ __align__(16) __half g_hb16[3][ND64];
__device__ __align__(16) __half g_beh16[3][ND64];
__device__ __align__(16) __half g_w16[3][ND64];
__device__ float  g_dinv[4 * NND];
__device__ int    g_deg[4 * NND];
__device__ int    g_part[4 * NCH];
__device__ int    g_ptr[4 * (NND + 1)];
__device__ int    g_cnt[4 * NND];
__device__ int    g_csr[E_TOT];
__device__ int    g_mark[NND];
__device__ float  g_sc[2];

/* ---------------- helpers ---------------- */
__device__ __forceinline__ float warp_sum(float v) {
#pragma unroll
    for (int o = 16; o; o >>= 1) v += __shfl_xor_sync(0xffffffffu, v, o);
    return v;
}
__device__ __forceinline__ float hsum8(float v) {
#pragma unroll
    for (int o = 4; o; o >>= 1) v += __shfl_xor_sync(0xffffffffu, v, o);
    return v;
}
__device__ __forceinline__ uint32_t f2h2(float2 v) {
    __half2 h = __floats2half2_rn(v.x, v.y);
    return *(uint32_t*)&h;
}
__device__ __forceinline__ float2 h22f2(uint32_t u) {
    return __half22float2(*(__half2*)&u);
}
__device__ __forceinline__ uint2 f4h4(float4 v) {
    return make_uint2(f2h2(make_float2(v.x, v.y)), f2h2(make_float2(v.z, v.w)));
}

__device__ __forceinline__ void mma16816(float4& c, uint32_t a0, uint32_t a1,
                                         uint32_t a2, uint32_t a3,
                                         uint32_t b0, uint32_t b1) {
    asm volatile(
        "mma.sync.aligned.m16n8k16.row.col.f32.f16.f16.f32 "
        "{%0,%1,%2,%3}, {%4,%5,%6,%7}, {%8,%9}, {%0,%1,%2,%3};"
        : "+f"(c.x), "+f"(c.y), "+f"(c.z), "+f"(c.w)
        : "r"(a0), "r"(a1), "r"(a2), "r"(a3), "r"(b0), "r"(b1));
}

/* ====== FUSED: concat+sumsq | degcnt | mark ====== */
__global__ __launch_bounds__(256) void init_fused_k(
    const float* __restrict__ ue, const float* __restrict__ ie,
    const int* __restrict__ aei, const int* __restrict__ bei,
    const int* __restrict__ bd) {
    int blk = blockIdx.x;
    if (blk < NB_CONCAT) {
        int t = blk * 256 + threadIdx.x;
        float su = 0.0f, si = 0.0f;
        if (t < NND * 16) {
            int node = t >> 4, q = t & 15;
            float4 v;
            if (node < NU) {
                v = ((const float4*)ue)[node * 16 + q];
                su = v.x * v.x + v.y * v.y + v.z * v.z + v.w * v.w;
            } else {
                v = ((const float4*)ie)[(node - NU) * 16 + q];
                si = v.x * v.x + v.y * v.y + v.z * v.z + v.w * v.w;
            }
            ((uint2*)g_b16)[t] = f4h4(v);
        }
        su = warp_sum(su);
        si = warp_sum(si);
        __shared__ float smu[8], smi[8];
        int w = threadIdx.x >> 5, l = threadIdx.x & 31;
        if (l == 0) { smu[w] = su; smi[w] = si; }
        __syncthreads();
        if (threadIdx.x == 0) {
            float a = 0.f, b = 0.f;
#pragma unroll
            for (int q = 0; q < 8; q++) { a += smu[q]; b += smi[q]; }
            if (a != 0.f) atomicAdd(&g_sc[0], a);
            if (b != 0.f) atomicAdd(&g_sc[1], b);
        }
    } else if (blk < NB_CONCAT + NB_DEG) {
        int q = (blk - NB_CONCAT) * 256 + threadIdx.x;
        if (q >= E_TOT / 4) return;
        int4 d4;
        int g;
        if (q < E_GLOBAL / 4) {
            g = 0;
            d4 = ((const int4*)(aei + E_GLOBAL))[q];
        } else {
            int r = q - E_GLOBAL / 4;
            int b = r / (E_BEH / 4), o = r - b * (E_BEH / 4);
            g = 1 + b;
            d4 = ((const int4*)(bei + (b * 2 + 1) * E_BEH))[o];
        }
        int* deg = g_deg + g * NND;
        atomicAdd(&deg[d4.x], 1);
        atomicAdd(&deg[d4.y], 1);
        atomicAdd(&deg[d4.z], 1);
        atomicAdd(&deg[d4.w], 1);
    } else {
        int t = (blk - NB_CONCAT - NB_DEG) * 256 + threadIdx.x;
        if (t >= BATCH * 9) return;
        int k = t / 9, r = t - k * 9;
        int i = r / 3, c = r - i * 3;
        int val = bd[k * 9 + i * 3 + c];
        if (c == 0) g_mark[val] = 1;
        else        g_mark[NU + val] = 1;
    }
}

/* ---------------- CSR build ---------------- */
__global__ __launch_bounds__(SCB) void part_k() {
    __shared__ int sm[SCB];
    int b = blockIdx.x;
    int g = b / NCH, ch = b % NCH;
    int idx = ch * SCB + threadIdx.x;
    int v = (idx < NND) ? g_deg[g * NND + idx] : 0;
    sm[threadIdx.x] = v;
    __syncthreads();
    for (int o = SCB / 2; o; o >>= 1) {
        if (threadIdx.x < o) sm[threadIdx.x] += sm[threadIdx.x + o];
        __syncthreads();
    }
    if (threadIdx.x == 0) g_part[b] = sm[0];
}

__global__ __launch_bounds__(256) void scanpart_k(float* out) {
    __shared__ int sm[256];
    int g = blockIdx.x;
    if (g == 0 && threadIdx.x == 0) out[0] = 0.0f;
    int v = (threadIdx.x < NCH) ? g_part[g * NCH + threadIdx.x] : 0;
    sm[threadIdx.x] = v;
    __syncthreads();
    for (int o = 1; o < 256; o <<= 1) {
        int a = (threadIdx.x >= o) ? sm[threadIdx.x - o] : 0;
        __syncthreads();
        sm[threadIdx.x] += a;
        __syncthreads();
    }
    if (threadIdx.x < NCH) g_part[g * NCH + threadIdx.x] = sm[threadIdx.x] - v;
    if (threadIdx.x == NCH - 1) g_ptr[g * (NND + 1) + NND] = sm[threadIdx.x];
}

__global__ __launch_bounds__(SCB) void scan_k() {
    __shared__ int sm[SCB];
    int b = blockIdx.x;
    int g = b / NCH, ch = b % NCH;
    int idx = ch * SCB + threadIdx.x;
    int v = (idx < NND) ? g_deg[g * NND + idx] : 0;
    sm[threadIdx.x] = v;
    __syncthreads();
    for (int o = 1; o < SCB; o <<= 1) {
        int add = (threadIdx.x >= o) ? sm[threadIdx.x - o] : 0;
        __syncthreads();
        sm[threadIdx.x] += add;
        __syncthreads();
    }
    int excl = sm[threadIdx.x] - v + g_part[b];
    if (idx < NND) {
        g_ptr[g * (NND + 1) + idx] = excl;
        g_cnt[g * NND + idx]       = excl;
        g_dinv[g * NND + idx]      = (v > 0) ? rsqrtf((float)v) : 0.0f;
        g_deg[g * NND + idx]       = 0;
    }
}

/* --------- HMMA GEMM body --------- */
#define SAS 72
__device__ __forceinline__ void gemm_body(const __half* __restrict__ A16,
                                          const float* __restrict__ W,
                                          __half* __restrict__ HW, int row0,
                                          const float* __restrict__ dv) {
    __shared__ __half sA[128 * SAS];
    __shared__ __half sWt[64 * SAS];
    int tid = threadIdx.x;

#pragma unroll
    for (int i = 0; i < 4; i++) {
        int idx = tid + i * 256;
        int r = idx >> 3, c8 = idx & 7;
        uint4 u = make_uint4(0u, 0u, 0u, 0u);
        int row = row0 + r;
        if (row < NND) u = ((const uint4*)A16)[row * 8 + c8];
        *(uint4*)(sA + r * SAS + c8 * 8) = u;
    }
#pragma unroll
    for (int i = 0; i < 4; i++) {
        int idx = tid + i * 256;
        int k = idx >> 4, n4 = (idx & 15) * 4;
        float4 w = ((const float4*)W)[idx];
        sWt[(n4 + 0) * SAS + k] = __float2half_rn(w.x);
        sWt[(n4 + 1) * SAS + k] = __float2half_rn(w.y);
        sWt[(n4 + 2) * SAS + k] = __float2half_rn(w.z);
        sWt[(n4 + 3) * SAS + k] = __float2half_rn(w.w);
    }
    __syncthreads();

    int wid = tid >> 5, lane = tid & 31;
    int gq = lane >> 2, tg = lane & 3;
    int mrow = wid * 16;

    float4 acc[8];
#pragma unroll
    for (int n = 0; n < 8; n++) acc[n] = make_float4(0.f, 0.f, 0.f, 0.f);

#pragma unroll
    for (int ks = 0; ks < 4; ks++) {
        int k0 = ks * 16 + tg * 2;
        uint32_t a0 = *(uint32_t*)(sA + (mrow + gq) * SAS + k0);
        uint32_t a1 = *(uint32_t*)(sA + (mrow + gq + 8) * SAS + k0);
        uint32_t a2 = *(uint32_t*)(sA + (mrow + gq) * SAS + k0 + 8);
        uint32_t a3 = *(uint32_t*)(sA + (mrow + gq + 8) * SAS + k0 + 8);
#pragma unroll
        for (int n = 0; n < 8; n++) {
            uint32_t b0 = *(uint32_t*)(sWt + (n * 8 + gq) * SAS + k0);
            uint32_t b1 = *(uint32_t*)(sWt + (n * 8 + gq) * SAS + k0 + 8);
            mma16816(acc[n], a0, a1, a2, a3, b0, b1);
        }
    }

    int r0 = row0 + mrow + gq;
    int r1 = r0 + 8;
    float s0 = (r0 < NND) ? dv[r0] : 0.0f;
    float s1 = (r1 < NND) ? dv[r1] : 0.0f;
#pragma unroll
    for (int n = 0; n < 8; n++) {
        int col = n * 8 + tg * 2;
        if (r0 < NND)
            *(uint32_t*)(HW + r0 * 64 + col) = f2h2(make_float2(acc[n].x * s0, acc[n].y * s0));
        if (r1 < NND)
            *(uint32_t*)(HW + r1 * 64 + col) = f2h2(make_float2(acc[n].z * s1, acc[n].w * s1));
    }
}

/* ====== FUSED: global layer-1 GEMM | fill ====== */
__global__ __launch_bounds__(256) void fill_gemm_k(
    const int* __restrict__ aei, const int* __restrict__ bei,
    const float* __restrict__ gW) {
    if (blockIdx.x < GEMM_BLOCKS) {
        gemm_body(g_b16, gW, g_hw, blockIdx.x * 128, g_dinv);
        return;
    }
    int q = (blockIdx.x - GEMM_BLOCKS) * 256 + threadIdx.x;
    if (q >= E_TOT / 4) return;
    int4 s4, d4;
    int g, base;
    if (q < E_GLOBAL / 4) {
        g = 0;
        base = 0;
        s4 = ((const int4*)aei)[q];
        d4 = ((const int4*)(aei + E_GLOBAL))[q];
    } else {
        int r = q - E_GLOBAL / 4;
        int b = r / (E_BEH / 4), o = r - b * (E_BEH / 4);
        g = 1 + b;
        base = E_GLOBAL + b * E_BEH;
        s4 = ((const int4*)(bei + (b * 2) * E_BEH))[o];
        d4 = ((const int4*)(bei + (b * 2 + 1) * E_BEH))[o];
    }
    int* cnt = g_cnt + g * NND;
    int* csr = g_csr + base;
    csr[atomicAdd(&cnt[d4.x], 1)] = s4.x;
    csr[atomicAdd(&cnt[d4.y], 1)] = s4.y;
    csr[atomicAdd(&cnt[d4.z], 1)] = s4.z;
    csr[atomicAdd(&cnt[d4.w], 1)] = s4.w;
}

__global__ __launch_bounds__(256) void gemm_k(const float* __restrict__ W, int srcsel) {
    gemm_body(srcsel ? g_h16 : g_b16, W, g_hw, blockIdx.x * 128, g_dinv);
}

__global__ __launch_bounds__(256) void gemm3_k(const float* __restrict__ bW, int l) {
    int b = blockIdx.y;
    const __half* A16 = l ? g_hb16[b] : g_b16;
    gemm_body(A16, bW + (b * 2 + l) * 4096, g_hwb[b], blockIdx.x * 128,
              g_dinv + (1 + b) * NND);
}

/* ------- software-pipelined 8-lane gather core ------- */
struct F8 { float v[8]; };

#define ACC4(U)                                                           \
    do {                                                                  \
        float2 p0 = h22f2((U).x), p1 = h22f2((U).y);                      \
        float2 p2 = h22f2((U).z), p3 = h22f2((U).w);                      \
        acc[0] += p0.x; acc[1] += p0.y; acc[2] += p1.x; acc[3] += p1.y;   \
        acc[4] += p2.x; acc[5] += p2.y; acc[6] += p3.x; acc[7] += p3.y;   \
    } while (0)

__device__ __forceinline__ F8 gather_core8(
    const __half* __restrict__ HW, int csr_base, int g,
    const float* __restrict__ bias, int node, int sub, bool active) {

    const int* ptr = g_ptr + g * (NND + 1);
    const int* csr = g_csr + csr_base;
    const uint4* HW128 = (const uint4*)HW;
    int beg = 0, end = 0;
    if (active) { beg = ptr[node]; end = ptr[node + 1]; }

    float acc[8] = {};
    int k = beg;
    if (k + 4 <= end) {
        /* prologue: load first index group + first row group */
        int i0 = csr[k], i1 = csr[k + 1], i2 = csr[k + 2], i3 = csr[k + 3];
        k += 4;
        uint4 u0 = HW128[i0 * 8 + sub];
        uint4 u1 = HW128[i1 * 8 + sub];
        uint4 u2 = HW128[i2 * 8 + sub];
        uint4 u3 = HW128[i3 * 8 + sub];
        while (k + 4 <= end) {
            /* issue next index loads (independent of current rows) */
            int j0 = csr[k], j1 = csr[k + 1], j2 = csr[k + 2], j3 = csr[k + 3];
            k += 4;
            /* consume current rows while indices are in flight */
            ACC4(u0); ACC4(u1); ACC4(u2); ACC4(u3);
            /* issue next row loads */
            u0 = HW128[j0 * 8 + sub];
            u1 = HW128[j1 * 8 + sub];
            u2 = HW128[j2 * 8 + sub];
            u3 = HW128[j3 * 8 + sub];
        }
        ACC4(u0); ACC4(u1); ACC4(u2); ACC4(u3);
    }
    for (; k < end; k++) {
        uint4 u = HW128[csr[k] * 8 + sub];
        ACC4(u);
    }

    float dd = active ? g_dinv[g * NND + node] : 0.0f;
    float4 bv0 = ((const float4*)bias)[sub * 2];
    float4 bv1 = ((const float4*)bias)[sub * 2 + 1];
    F8 o;
    o.v[0] = acc[0] * dd + bv0.x; o.v[1] = acc[1] * dd + bv0.y;
    o.v[2] = acc[2] * dd + bv0.z; o.v[3] = acc[3] * dd + bv0.w;
    o.v[4] = acc[4] * dd + bv1.x; o.v[5] = acc[5] * dd + bv1.y;
    o.v[6] = acc[6] * dd + bv1.z; o.v[7] = acc[7] * dd + bv1.w;
    float ss = 0.f;
#pragma unroll
    for (int i = 0; i < 8; i++) ss += o.v[i] * o.v[i];
    ss = hsum8(ss);
    float inv = 1.0f / fmaxf(sqrtf(ss), 1e-12f);
#pragma unroll
    for (int i = 0; i < 8; i++) o.v[i] *= inv;
    return o;
}

__device__ __forceinline__ uint4 f8h8(const F8& h) {
    uint4 r;
    r.x = f2h2(make_float2(h.v[0], h.v[1]));
    r.y = f2h2(make_float2(h.v[2], h.v[3]));
    r.z = f2h2(make_float2(h.v[4], h.v[5]));
    r.w = f2h2(make_float2(h.v[6], h.v[7]));
    return r;
}
__device__ __forceinline__ F8 h8f8(uint4 u) {
    F8 r;
    float2 p0 = h22f2(u.x), p1 = h22f2(u.y);
    float2 p2 = h22f2(u.z), p3 = h22f2(u.w);
    r.v[0] = p0.x; r.v[1] = p0.y; r.v[2] = p1.x; r.v[3] = p1.y;
    r.v[4] = p2.x; r.v[5] = p2.y; r.v[6] = p3.x; r.v[7] = p3.y;
    return r;
}

/* global gather: 4 nodes/warp; base fp16 in-place */
__global__ __launch_bounds__(256) void gather_k(const float* __restrict__ bias, int mode) {
    int t = blockIdx.x * blockDim.x + threadIdx.x;
    int w = t >> 5, lane = t & 31;
    if (w >= NND4) return;
    int sub = lane & 7;
    int node = w * 4 + (lane >> 3);
    bool act = node < NND;
    F8 h = gather_core8(g_hw, 0, 0, bias, node, sub, act);
    if (!act) return;
    int offq = node * 8 + sub;
    F8 r = h8f8(((const uint4*)g_b16)[offq]);
    float sc = (mode == 0) ? 1.0f : 0.5f;
    F8 nb;
#pragma unroll
    for (int i = 0; i < 8; i++) nb.v[i] = r.v[i] + sc * h.v[i];
    ((uint4*)g_b16)[offq] = f8h8(nb);
    if (mode == 0) ((uint4*)g_h16)[offq] = f8h8(h);
}

/* behavioral layer 0 gather */
__global__ __launch_bounds__(256) void gather3_k(const float* __restrict__ bb) {
    int t = blockIdx.x * blockDim.x + threadIdx.x;
    int w = t >> 5, lane = t & 31;
    if (w >= 3 * NND4) return;
    int b = w / NND4, i = w - b * NND4;
    int sub = lane & 7;
    int node = i * 4 + (lane >> 3);
    bool act = node < NND;
    F8 h = gather_core8(g_hwb[b], E_GLOBAL + b * E_BEH, 1 + b,
                        bb + (b * 2) * 64, node, sub, act);
    if (!act) return;
    int offq = node * 8 + sub;
    ((uint4*)g_hb16[b])[offq] = f8h8(h);
    F8 r = h8f8(((const uint4*)g_b16)[offq]);
    F8 res;
#pragma unroll
    for (int j = 0; j < 8; j++) res.v[j] = r.v[j] + h.v[j];
    ((uint4*)g_beh16[b])[offq] = f8h8(res);
}

/* behavioral layer 1 gather + attention + combine — marked nodes; unmarks */
__global__ __launch_bounds__(256) void gather3attn_k(const float* __restrict__ bb) {
    int t = blockIdx.x * blockDim.x + threadIdx.x;
    int w = t >> 5, lane = t & 31;
    if (w >= NND4) return;
    int sub = lane & 7;
    int node = w * 4 + (lane >> 3);
    bool act = (node < NND) && (g_mark[node] != 0);
    if (__ballot_sync(0xffffffffu, act) == 0u) return;
    int offq = node * 8 + sub;

    F8 tok[3];
#pragma unroll
    for (int b = 0; b < 3; b++) {
        F8 h = gather_core8(g_hwb[b], E_GLOBAL + b * E_BEH, 1 + b,
                            bb + (b * 2 + 1) * 64, node, sub, act);
        F8 r = {};
        if (act) r = h8f8(((const uint4*)g_beh16[b])[offq]);
#pragma unroll
        for (int i = 0; i < 8; i++) tok[b].v[i] = r.v[i] + 0.5f * h.v[i];
    }

    float d00 = 0.f, d01 = 0.f, d02 = 0.f, d11 = 0.f, d12 = 0.f, d22 = 0.f;
#pragma unroll
    for (int i = 0; i < 8; i++) {
        d00 += tok[0].v[i] * tok[0].v[i];
        d01 += tok[0].v[i] * tok[1].v[i];
        d02 += tok[0].v[i] * tok[2].v[i];
        d11 += tok[1].v[i] * tok[1].v[i];
        d12 += tok[1].v[i] * tok[2].v[i];
        d22 += tok[2].v[i] * tok[2].v[i];
    }
    float s00 = hsum8(d00), s01 = hsum8(d01), s02 = hsum8(d02);
    float s11 = hsum8(d11), s12 = hsum8(d12), s22 = hsum8(d22);

    if (!act) return;

    const float sc = 0.125f;
    float s[3][3] = {{s00 * sc, s01 * sc, s02 * sc},
                     {s01 * sc, s11 * sc, s12 * sc},
                     {s02 * sc, s12 * sc, s22 * sc}};

    bool isU = node < NU;
    float gw = isU ? 2.35f : 1.0f;
    float bw = isU ? 0.242f : 0.55f;
    F8 gvv = h8f8(((const uint4*)g_b16)[offq]);

#pragma unroll
    for (int b = 0; b < 3; b++) {
        float m  = fmaxf(s[b][0], fmaxf(s[b][1], s[b][2]));
        float e0 = __expf(s[b][0] - m), e1 = __expf(s[b][1] - m), e2 = __expf(s[b][2] - m);
        float is = 1.0f / (e0 + e1 + e2);
        float a0 = e0 * is, a1 = e1 * is, a2 = e2 * is;
        F8 o;
#pragma unroll
        for (int i = 0; i < 8; i++)
            o.v[i] = gw * gvv.v[i] + bw * (a0 * tok[0].v[i] + a1 * tok[1].v[i] + a2 * tok[2].v[i]);
        ((uint4*)g_w16[b])[offq] = f8h8(o);
    }
    if (sub == 0) g_mark[node] = 0;
}

/* ---------------- BPR loss + fused regularizer; restores g_sc ---------------- */
__global__ void loss_k(const int* __restrict__ bd, float* out) {
    int t = blockIdx.x * blockDim.x + threadIdx.x;
    int w = t >> 5, lane = t & 31;
    float partial = 0.0f;
    if (w < BATCH * 9) {
        int k = w / 9, pr = w - k * 9;
        int i = pr / 3, j = pr - i * 3;
        int u   = bd[k * 9 + i * 3 + 0];
        int ip  = bd[k * 9 + i * 3 + 1];
        int in_ = bd[k * 9 + i * 3 + 2];
        float2 uu = h22f2(((const uint32_t*)g_w16[i])[u * 32 + lane]);
        float2 pp = h22f2(((const uint32_t*)g_w16[j])[(NU + ip) * 32 + lane]);
        float2 nn = h22f2(((const uint32_t*)g_w16[j])[(NU + in_) * 32 + lane]);
        float sp = warp_sum(uu.x * pp.x + uu.y * pp.y);
        float sn = warp_sum(uu.x * nn.x + uu.y * nn.y);
        float x  = sp - sn;
        float ls = fminf(x, 0.0f) - log1pf(expf(-fabsf(x)));
        partial = -ls * (1.0f / (float)BATCH);
    }
    __shared__ float sm[8];
    if (lane == 0) sm[threadIdx.x >> 5] = partial;
    __syncthreads();
    if (threadIdx.x == 0) {
        float s = 0.0f;
#pragma unroll
        for (int q = 0; q < 8; q++) s += sm[q];
        if (blockIdx.x == 0) {
            s += 0.001f * ((sqrtf(g_sc[0]) + sqrtf(g_sc[1])) / (float)(N_ITEMS + 1));
            g_sc[0] = 0.0f;
            g_sc[1] = 0.0f;
        }
        atomicAdd(out, s);
    }
}

/* ================================ launch ================================ */
extern "C" void kernel_launch(void* const* d_in, const int* in_sizes, int n_in,
                              void* d_out, int out_size) {
    const float* ue  = (const float*)d_in[0];
    const float* ie  = (const float*)d_in[1];
    const float* gW  = (const float*)d_in[2];
    const float* gb  = (const float*)d_in[3];
    const float* bW  = (const float*)d_in[4];
    const float* bb  = (const float*)d_in[5];
    const int*   aei = (const int*)d_in[6];
    const int*   bei = (const int*)d_in[7];
    const int*   bd  = (const int*)d_in[8];
    float* out = (float*)d_out;

    const int T = 256;
    dim3 blk(T);

    init_fused_k<<<NB_CONCAT + NB_DEG + NB_MARK, blk>>>(ue, ie, aei, bei, bd);

    part_k<<<4 * NCH, SCB>>>();
    scanpart_k<<<4, 256>>>(out);
    scan_k<<<4 * NCH, SCB>>>();

    fill_gemm_k<<<GEMM_BLOCKS + NB_FILL, blk>>>(aei, bei, gW);

    const int GW_BLOCKS  = (NND4 * 32 + T - 1) / T;
    const int GW3_BLOCKS = (3 * NND4 * 32 + T - 1) / T;

    gather_k<<<GW_BLOCKS, blk>>>(gb, 0);
    gemm_k<<<GEMM_BLOCKS, 256>>>(gW + 4096, 1);
    gather_k<<<GW_BLOCKS, blk>>>(gb + 64, 1);

    dim3 g3(GEMM_BLOCKS, 3);
    gemm3_k<<<g3, 256>>>(bW, 0);
    gather3_k<<<GW3_BLOCKS, blk>>>(bb);
    gemm3_k<<<g3, 256>>>(bW, 1);
    gather3attn_k<<<GW_BLOCKS, blk>>>(bb);

    loss_k<<<(BATCH * 9 * 32 + T - 1) / T, blk>>>(bd, out);
}

// round 16
// speedup vs baseline: 1.1039x; 1.0173x over previous
#include <cuda_runtime.h>
#include <cuda_fp16.h>
#include <math.h>
#include <stdint.h>

#define N_USERS 60000
#define N_ITEMS 40000
#define NU      60001
#define NND     100002
#define NND4    ((NND + 3) / 4)
#define D       64
#define ND64    (NND * 64)
#define E_GLOBAL 1000000
#define E_BEH    500000
#define E_TOT   (E_GLOBAL + 3 * E_BEH)
#define BATCH    4096

#define SCB 512
#define NCH ((NND + SCB - 1) / SCB)

#define NB_CONCAT ((NND * 16 + 255) / 256)
#define NB_DEG    ((E_TOT / 4 + 255) / 256)
#define NB_MARK   ((BATCH * 9 + 255) / 256)
#define GEMM_BLOCKS ((NND + 127) / 128)
#define NB_FILL   ((E_TOT / 4 + 255) / 256)

/* ------- scratch. INVARIANT: g_deg, g_mark, g_sc, g_total zero at entry;
   restored to zero by their last readers each execution. ------- */
__device__ __align__(16) __half g_hw[ND64];
__device__ __align__(16) __half g_hwb[3][ND64];
__device__ __align__(16) __half g_b16[ND64];
__device__ __align__(16) __half g_h16[ND64];
__device__ __align__(16) __half g_hb16[3][ND64];
__device__ __align__(16) __half g_beh16[3][ND64];
__device__ __align__(16) __half g_w16[3][ND64];
__device__ float  g_dinv[4 * NND];
__device__ int    g_deg[4 * NND];
__device__ int    g_ptr[4 * NND];      /* segment begin per node */
__device__ int    g_cnt[4 * NND];      /* fill cursor; == segment end after fill */
__device__ int    g_csr[E_TOT];
__device__ int    g_mark[NND];
__device__ int    g_total[4];
__device__ float  g_sc[2];

/* ---------------- helpers ---------------- */
__device__ __forceinline__ float warp_sum(float v) {
#pragma unroll
    for (int o = 16; o; o >>= 1) v += __shfl_xor_sync(0xffffffffu, v, o);
    return v;
}
__device__ __forceinline__ float hsum8(float v) {
#pragma unroll
    for (int o = 4; o; o >>= 1) v += __shfl_xor_sync(0xffffffffu, v, o);
    return v;
}
__device__ __forceinline__ uint32_t f2h2(float2 v) {
    __half2 h = __floats2half2_rn(v.x, v.y);
    return *(uint32_t*)&h;
}
__device__ __forceinline__ float2 h22f2(uint32_t u) {
    return __half22float2(*(__half2*)&u);
}
__device__ __forceinline__ uint2 f4h4(float4 v) {
    return make_uint2(f2h2(make_float2(v.x, v.y)), f2h2(make_float2(v.z, v.w)));
}

__device__ __forceinline__ void mma16816(float4& c, uint32_t a0, uint32_t a1,
                                         uint32_t a2, uint32_t a3,
                                         uint32_t b0, uint32_t b1) {
    asm volatile(
        "mma.sync.aligned.m16n8k16.row.col.f32.f16.f16.f32 "
        "{%0,%1,%2,%3}, {%4,%5,%6,%7}, {%8,%9}, {%0,%1,%2,%3};"
        : "+f"(c.x), "+f"(c.y), "+f"(c.z), "+f"(c.w)
        : "r"(a0), "r"(a1), "r"(a2), "r"(a3), "r"(b0), "r"(b1));
}

/* ====== FUSED: concat+sumsq | degcnt | mark ====== */
__global__ __launch_bounds__(256) void init_fused_k(
    const float* __restrict__ ue, const float* __restrict__ ie,
    const int* __restrict__ aei, const int* __restrict__ bei,
    const int* __restrict__ bd) {
    int blk = blockIdx.x;
    if (blk < NB_CONCAT) {
        int t = blk * 256 + threadIdx.x;
        float su = 0.0f, si = 0.0f;
        if (t < NND * 16) {
            int node = t >> 4, q = t & 15;
            float4 v;
            if (node < NU) {
                v = ((const float4*)ue)[node * 16 + q];
                su = v.x * v.x + v.y * v.y + v.z * v.z + v.w * v.w;
            } else {
                v = ((const float4*)ie)[(node - NU) * 16 + q];
                si = v.x * v.x + v.y * v.y + v.z * v.z + v.w * v.w;
            }
            ((uint2*)g_b16)[t] = f4h4(v);
        }
        su = warp_sum(su);
        si = warp_sum(si);
        __shared__ float smu[8], smi[8];
        int w = threadIdx.x >> 5, l = threadIdx.x & 31;
        if (l == 0) { smu[w] = su; smi[w] = si; }
        __syncthreads();
        if (threadIdx.x == 0) {
            float a = 0.f, b = 0.f;
#pragma unroll
            for (int q = 0; q < 8; q++) { a += smu[q]; b += smi[q]; }
            if (a != 0.f) atomicAdd(&g_sc[0], a);
            if (b != 0.f) atomicAdd(&g_sc[1], b);
        }
    } else if (blk < NB_CONCAT + NB_DEG) {
        int q = (blk - NB_CONCAT) * 256 + threadIdx.x;
        if (q >= E_TOT / 4) return;
        int4 d4;
        int g;
        if (q < E_GLOBAL / 4) {
            g = 0;
            d4 = ((const int4*)(aei + E_GLOBAL))[q];
        } else {
            int r = q - E_GLOBAL / 4;
            int b = r / (E_BEH / 4), o = r - b * (E_BEH / 4);
            g = 1 + b;
            d4 = ((const int4*)(bei + (b * 2 + 1) * E_BEH))[o];
        }
        int* deg = g_deg + g * NND;
        atomicAdd(&deg[d4.x], 1);
        atomicAdd(&deg[d4.y], 1);
        atomicAdd(&deg[d4.z], 1);
        atomicAdd(&deg[d4.w], 1);
    } else {
        int t = (blk - NB_CONCAT - NB_DEG) * 256 + threadIdx.x;
        if (t >= BATCH * 9) return;
        int k = t / 9, r = t - k * 9;
        int i = r / 3, c = r - i * 3;
        int val = bd[k * 9 + i * 3 + c];
        if (c == 0) g_mark[val] = 1;
        else        g_mark[NU + val] = 1;
    }
}

/* ---- single-kernel CSR allocation: block scan + atomic base; fused dinv;
       restores g_deg = 0; zeroes out[0] ---- */
__global__ __launch_bounds__(SCB) void alloc_k(float* out) {
    __shared__ int sm[SCB];
    __shared__ int sbase;
    int b = blockIdx.x;
    int g = b / NCH, ch = b % NCH;
    int idx = ch * SCB + threadIdx.x;
    if (b == 0 && threadIdx.x == 0) out[0] = 0.0f;
    int v = (idx < NND) ? g_deg[g * NND + idx] : 0;
    sm[threadIdx.x] = v;
    __syncthreads();
    for (int o = 1; o < SCB; o <<= 1) {
        int add = (threadIdx.x >= o) ? sm[threadIdx.x - o] : 0;
        __syncthreads();
        sm[threadIdx.x] += add;
        __syncthreads();
    }
    if (threadIdx.x == SCB - 1) sbase = atomicAdd(&g_total[g], sm[SCB - 1]);
    __syncthreads();
    int beg = sbase + sm[threadIdx.x] - v;
    if (idx < NND) {
        g_ptr[g * NND + idx]  = beg;
        g_cnt[g * NND + idx]  = beg;
        g_dinv[g * NND + idx] = (v > 0) ? rsqrtf((float)v) : 0.0f;
        g_deg[g * NND + idx]  = 0;   /* restore invariant */
    }
}

/* --------- HMMA GEMM body --------- */
#define SAS 72
__device__ __forceinline__ void gemm_body(const __half* __restrict__ A16,
                                          const float* __restrict__ W,
                                          __half* __restrict__ HW, int row0,
                                          const float* __restrict__ dv) {
    __shared__ __half sA[128 * SAS];
    __shared__ __half sWt[64 * SAS];
    int tid = threadIdx.x;

#pragma unroll
    for (int i = 0; i < 4; i++) {
        int idx = tid + i * 256;
        int r = idx >> 3, c8 = idx & 7;
        uint4 u = make_uint4(0u, 0u, 0u, 0u);
        int row = row0 + r;
        if (row < NND) u = ((const uint4*)A16)[row * 8 + c8];
        *(uint4*)(sA + r * SAS + c8 * 8) = u;
    }
#pragma unroll
    for (int i = 0; i < 4; i++) {
        int idx = tid + i * 256;
        int k = idx >> 4, n4 = (idx & 15) * 4;
        float4 w = ((const float4*)W)[idx];
        sWt[(n4 + 0) * SAS + k] = __float2half_rn(w.x);
        sWt[(n4 + 1) * SAS + k] = __float2half_rn(w.y);
        sWt[(n4 + 2) * SAS + k] = __float2half_rn(w.z);
        sWt[(n4 + 3) * SAS + k] = __float2half_rn(w.w);
    }
    __syncthreads();

    int wid = tid >> 5, lane = tid & 31;
    int gq = lane >> 2, tg = lane & 3;
    int mrow = wid * 16;

    float4 acc[8];
#pragma unroll
    for (int n = 0; n < 8; n++) acc[n] = make_float4(0.f, 0.f, 0.f, 0.f);

#pragma unroll
    for (int ks = 0; ks < 4; ks++) {
        int k0 = ks * 16 + tg * 2;
        uint32_t a0 = *(uint32_t*)(sA + (mrow + gq) * SAS + k0);
        uint32_t a1 = *(uint32_t*)(sA + (mrow + gq + 8) * SAS + k0);
        uint32_t a2 = *(uint32_t*)(sA + (mrow + gq) * SAS + k0 + 8);
        uint32_t a3 = *(uint32_t*)(sA + (mrow + gq + 8) * SAS + k0 + 8);
#pragma unroll
        for (int n = 0; n < 8; n++) {
            uint32_t b0 = *(uint32_t*)(sWt + (n * 8 + gq) * SAS + k0);
            uint32_t b1 = *(uint32_t*)(sWt + (n * 8 + gq) * SAS + k0 + 8);
            mma16816(acc[n], a0, a1, a2, a3, b0, b1);
        }
    }

    int r0 = row0 + mrow + gq;
    int r1 = r0 + 8;
    float s0 = (r0 < NND) ? dv[r0] : 0.0f;
    float s1 = (r1 < NND) ? dv[r1] : 0.0f;
#pragma unroll
    for (int n = 0; n < 8; n++) {
        int col = n * 8 + tg * 2;
        if (r0 < NND)
            *(uint32_t*)(HW + r0 * 64 + col) = f2h2(make_float2(acc[n].x * s0, acc[n].y * s0));
        if (r1 < NND)
            *(uint32_t*)(HW + r1 * 64 + col) = f2h2(make_float2(acc[n].z * s1, acc[n].w * s1));
    }
}

/* ====== FUSED: global layer-1 GEMM | fill ====== */
__global__ __launch_bounds__(256) void fill_gemm_k(
    const int* __restrict__ aei, const int* __restrict__ bei,
    const float* __restrict__ gW) {
    if (blockIdx.x < GEMM_BLOCKS) {
        gemm_body(g_b16, gW, g_hw, blockIdx.x * 128, g_dinv);
        return;
    }
    int q = (blockIdx.x - GEMM_BLOCKS) * 256 + threadIdx.x;
    if (q >= E_TOT / 4) return;
    int4 s4, d4;
    int g, base;
    if (q < E_GLOBAL / 4) {
        g = 0;
        base = 0;
        s4 = ((const int4*)aei)[q];
        d4 = ((const int4*)(aei + E_GLOBAL))[q];
    } else {
        int r = q - E_GLOBAL / 4;
        int b = r / (E_BEH / 4), o = r - b * (E_BEH / 4);
        g = 1 + b;
        base = E_GLOBAL + b * E_BEH;
        s4 = ((const int4*)(bei + (b * 2) * E_BEH))[o];
        d4 = ((const int4*)(bei + (b * 2 + 1) * E_BEH))[o];
    }
    int* cnt = g_cnt + g * NND;
    int* csr = g_csr + base;
    csr[atomicAdd(&cnt[d4.x], 1)] = s4.x;
    csr[atomicAdd(&cnt[d4.y], 1)] = s4.y;
    csr[atomicAdd(&cnt[d4.z], 1)] = s4.z;
    csr[atomicAdd(&cnt[d4.w], 1)] = s4.w;
}

__global__ __launch_bounds__(256) void gemm_k(const float* __restrict__ W, int srcsel) {
    gemm_body(srcsel ? g_h16 : g_b16, W, g_hw, blockIdx.x * 128, g_dinv);
}

__global__ __launch_bounds__(256) void gemm3_k(const float* __restrict__ bW, int l) {
    int b = blockIdx.y;
    const __half* A16 = l ? g_hb16[b] : g_b16;
    gemm_body(A16, bW + (b * 2 + l) * 4096, g_hwb[b], blockIdx.x * 128,
              g_dinv + (1 + b) * NND);
}

/* ------- software-pipelined 8-lane gather core (beg from g_ptr, end from g_cnt) ------- */
struct F8 { float v[8]; };

#define ACC4(U)                                                           \
    do {                                                                  \
        float2 p0 = h22f2((U).x), p1 = h22f2((U).y);                      \
        float2 p2 = h22f2((U).z), p3 = h22f2((U).w);                      \
        acc[0] += p0.x; acc[1] += p0.y; acc[2] += p1.x; acc[3] += p1.y;   \
        acc[4] += p2.x; acc[5] += p2.y; acc[6] += p3.x; acc[7] += p3.y;   \
    } while (0)

__device__ __forceinline__ F8 gather_core8(
    const __half* __restrict__ HW, int csr_base, int g,
    const float* __restrict__ bias, int node, int sub, bool active) {

    const int* csr = g_csr + csr_base;
    const uint4* HW128 = (const uint4*)HW;
    int beg = 0, end = 0;
    if (active) {
        beg = g_ptr[g * NND + node];
        end = g_cnt[g * NND + node];
    }

    float acc[8] = {};
    int k = beg;
    if (k + 4 <= end) {
        int i0 = csr[k], i1 = csr[k + 1], i2 = csr[k + 2], i3 = csr[k + 3];
        k += 4;
        uint4 u0 = HW128[i0 * 8 + sub];
        uint4 u1 = HW128[i1 * 8 + sub];
        uint4 u2 = HW128[i2 * 8 + sub];
        uint4 u3 = HW128[i3 * 8 + sub];
        while (k + 4 <= end) {
            int j0 = csr[k], j1 = csr[k + 1], j2 = csr[k + 2], j3 = csr[k + 3];
            k += 4;
            ACC4(u0); ACC4(u1); ACC4(u2); ACC4(u3);
            u0 = HW128[j0 * 8 + sub];
            u1 = HW128[j1 * 8 + sub];
            u2 = HW128[j2 * 8 + sub];
            u3 = HW128[j3 * 8 + sub];
        }
        ACC4(u0); ACC4(u1); ACC4(u2); ACC4(u3);
    }
    for (; k < end; k++) {
        uint4 u = HW128[csr[k] * 8 + sub];
        ACC4(u);
    }

    float dd = active ? g_dinv[g * NND + node] : 0.0f;
    float4 bv0 = ((const float4*)bias)[sub * 2];
    float4 bv1 = ((const float4*)bias)[sub * 2 + 1];
    F8 o;
    o.v[0] = acc[0] * dd + bv0.x; o.v[1] = acc[1] * dd + bv0.y;
    o.v[2] = acc[2] * dd + bv0.z; o.v[3] = acc[3] * dd + bv0.w;
    o.v[4] = acc[4] * dd + bv1.x; o.v[5] = acc[5] * dd + bv1.y;
    o.v[6] = acc[6] * dd + bv1.z; o.v[7] = acc[7] * dd + bv1.w;
    float ss = 0.f;
#pragma unroll
    for (int i = 0; i < 8; i++) ss += o.v[i] * o.v[i];
    ss = hsum8(ss);
    float inv = 1.0f / fmaxf(sqrtf(ss), 1e-12f);
#pragma unroll
    for (int i = 0; i < 8; i++) o.v[i] *= inv;
    return o;
}

__device__ __forceinline__ uint4 f8h8(const F8& h) {
    uint4 r;
    r.x = f2h2(make_float2(h.v[0], h.v[1]));
    r.y = f2h2(make_float2(h.v[2], h.v[3]));
    r.z = f2h2(make_float2(h.v[4], h.v[5]));
    r.w = f2h2(make_float2(h.v[6], h.v[7]));
    return r;
}
__device__ __forceinline__ F8 h8f8(uint4 u) {
    F8 r;
    float2 p0 = h22f2(u.x), p1 = h22f2(u.y);
    float2 p2 = h22f2(u.z), p3 = h22f2(u.w);
    r.v[0] = p0.x; r.v[1] = p0.y; r.v[2] = p1.x; r.v[3] = p1.y;
    r.v[4] = p2.x; r.v[5] = p2.y; r.v[6] = p3.x; r.v[7] = p3.y;
    return r;
}

/* global gather: 4 nodes/warp; base fp16 in-place */
__global__ __launch_bounds__(256) void gather_k(const float* __restrict__ bias, int mode) {
    int t = blockIdx.x * blockDim.x + threadIdx.x;
    int w = t >> 5, lane = t & 31;
    if (w >= NND4) return;
    int sub = lane & 7;
    int node = w * 4 + (lane >> 3);
    bool act = node < NND;
    F8 h = gather_core8(g_hw, 0, 0, bias, node, sub, act);
    if (!act) return;
    int offq = node * 8 + sub;
    F8 r = h8f8(((const uint4*)g_b16)[offq]);
    float sc = (mode == 0) ? 1.0f : 0.5f;
    F8 nb;
#pragma unroll
    for (int i = 0; i < 8; i++) nb.v[i] = r.v[i] + sc * h.v[i];
    ((uint4*)g_b16)[offq] = f8h8(nb);
    if (mode == 0) ((uint4*)g_h16)[offq] = f8h8(h);
}

/* behavioral layer 0 gather; res stored only for marked nodes */
__global__ __launch_bounds__(256) void gather3_k(const float* __restrict__ bb) {
    int t = blockIdx.x * blockDim.x + threadIdx.x;
    int w = t >> 5, lane = t & 31;
    if (w >= 3 * NND4) return;
    int b = w / NND4, i = w - b * NND4;
    int sub = lane & 7;
    int node = i * 4 + (lane >> 3);
    bool act = node < NND;
    F8 h = gather_core8(g_hwb[b], E_GLOBAL + b * E_BEH, 1 + b,
                        bb + (b * 2) * 64, node, sub, act);
    if (!act) return;
    int offq = node * 8 + sub;
    ((uint4*)g_hb16[b])[offq] = f8h8(h);
    if (g_mark[node]) {
        F8 r = h8f8(((const uint4*)g_b16)[offq]);
        F8 res;
#pragma unroll
        for (int j = 0; j < 8; j++) res.v[j] = r.v[j] + h.v[j];
        ((uint4*)g_beh16[b])[offq] = f8h8(res);
    }
}

/* behavioral layer 1 gather + attention + combine — marked nodes; unmarks */
__global__ __launch_bounds__(256) void gather3attn_k(const float* __restrict__ bb) {
    int t = blockIdx.x * blockDim.x + threadIdx.x;
    int w = t >> 5, lane = t & 31;
    if (w >= NND4) return;
    int sub = lane & 7;
    int node = w * 4 + (lane >> 3);
    bool act = (node < NND) && (g_mark[node] != 0);
    if (__ballot_sync(0xffffffffu, act) == 0u) return;
    int offq = node * 8 + sub;

    F8 tok[3];
#pragma unroll
    for (int b = 0; b < 3; b++) {
        F8 h = gather_core8(g_hwb[b], E_GLOBAL + b * E_BEH, 1 + b,
                            bb + (b * 2 + 1) * 64, node, sub, act);
        F8 r = {};
        if (act) r = h8f8(((const uint4*)g_beh16[b])[offq]);
#pragma unroll
        for (int i = 0; i < 8; i++) tok[b].v[i] = r.v[i] + 0.5f * h.v[i];
    }

    float d00 = 0.f, d01 = 0.f, d02 = 0.f, d11 = 0.f, d12 = 0.f, d22 = 0.f;
#pragma unroll
    for (int i = 0; i < 8; i++) {
        d00 += tok[0].v[i] * tok[0].v[i];
        d01 += tok[0].v[i] * tok[1].v[i];
        d02 += tok[0].v[i] * tok[2].v[i];
        d11 += tok[1].v[i] * tok[1].v[i];
        d12 += tok[1].v[i] * tok[2].v[i];
        d22 += tok[2].v[i] * tok[2].v[i];
    }
    float s00 = hsum8(d00), s01 = hsum8(d01), s02 = hsum8(d02);
    float s11 = hsum8(d11), s12 = hsum8(d12), s22 = hsum8(d22);

    if (!act) return;

    const float sc = 0.125f;
    float s[3][3] = {{s00 * sc, s01 * sc, s02 * sc},
                     {s01 * sc, s11 * sc, s12 * sc},
                     {s02 * sc, s12 * sc, s22 * sc}};

    bool isU = node < NU;
    float gw = isU ? 2.35f : 1.0f;
    float bw = isU ? 0.242f : 0.55f;
    F8 gvv = h8f8(((const uint4*)g_b16)[offq]);

#pragma unroll
    for (int b = 0; b < 3; b++) {
        float m  = fmaxf(s[b][0], fmaxf(s[b][1], s[b][2]));
        float e0 = __expf(s[b][0] - m), e1 = __expf(s[b][1] - m), e2 = __expf(s[b][2] - m);
        float is = 1.0f / (e0 + e1 + e2);
        float a0 = e0 * is, a1 = e1 * is, a2 = e2 * is;
        F8 o;
#pragma unroll
        for (int i = 0; i < 8; i++)
            o.v[i] = gw * gvv.v[i] + bw * (a0 * tok[0].v[i] + a1 * tok[1].v[i] + a2 * tok[2].v[i]);
        ((uint4*)g_w16[b])[offq] = f8h8(o);
    }
    if (sub == 0) g_mark[node] = 0;
}

/* ---------------- BPR loss + regularizer; restores g_sc, g_total ---------------- */
__global__ void loss_k(const int* __restrict__ bd, float* out) {
    int t = blockIdx.x * blockDim.x + threadIdx.x;
    int w = t >> 5, lane = t & 31;
    float partial = 0.0f;
    if (w < BATCH * 9) {
        int k = w / 9, pr = w - k * 9;
        int i = pr / 3, j = pr - i * 3;
        int u   = bd[k * 9 + i * 3 + 0];
        int ip  = bd[k * 9 + i * 3 + 1];
        int in_ = bd[k * 9 + i * 3 + 2];
        float2 uu = h22f2(((const uint32_t*)g_w16[i])[u * 32 + lane]);
        float2 pp = h22f2(((const uint32_t*)g_w16[j])[(NU + ip) * 32 + lane]);
        float2 nn = h22f2(((const uint32_t*)g_w16[j])[(NU + in_) * 32 + lane]);
        float sp = warp_sum(uu.x * pp.x + uu.y * pp.y);
        float sn = warp_sum(uu.x * nn.x + uu.y * nn.y);
        float x  = sp - sn;
        float ls = fminf(x, 0.0f) - log1pf(expf(-fabsf(x)));
        partial = -ls * (1.0f / (float)BATCH);
    }
    __shared__ float sm[8];
    if (lane == 0) sm[threadIdx.x >> 5] = partial;
    __syncthreads();
    if (threadIdx.x == 0) {
        float s = 0.0f;
#pragma unroll
        for (int q = 0; q < 8; q++) s += sm[q];
        if (blockIdx.x == 0) {
            s += 0.001f * ((sqrtf(g_sc[0]) + sqrtf(g_sc[1])) / (float)(N_ITEMS + 1));
            g_sc[0] = 0.0f;
            g_sc[1] = 0.0f;
            g_total[0] = 0; g_total[1] = 0; g_total[2] = 0; g_total[3] = 0;
        }
        atomicAdd(out, s);
    }
}

/* ================================ launch ================================ */
extern "C" void kernel_launch(void* const* d_in, const int* in_sizes, int n_in,
                              void* d_out, int out_size) {
    const float* ue  = (const float*)d_in[0];
    const float* ie  = (const float*)d_in[1];
    const float* gW  = (const float*)d_in[2];
    const float* gb  = (const float*)d_in[3];
    const float* bW  = (const float*)d_in[4];
    const float* bb  = (const float*)d_in[5];
    const int*   aei = (const int*)d_in[6];
    const int*   bei = (const int*)d_in[7];
    const int*   bd  = (const int*)d_in[8];
    float* out = (float*)d_out;

    const int T = 256;
    dim3 blk(T);

    init_fused_k<<<NB_CONCAT + NB_DEG + NB_MARK, blk>>>(ue, ie, aei, bei, bd);
    alloc_k<<<4 * NCH, SCB>>>(out);
    fill_gemm_k<<<GEMM_BLOCKS + NB_FILL, blk>>>(aei, bei, gW);

    const int GW_BLOCKS  = (NND4 * 32 + T - 1) / T;
    const int GW3_BLOCKS = (3 * NND4 * 32 + T - 1) / T;

    gather_k<<<GW_BLOCKS, blk>>>(gb, 0);
    gemm_k<<<GEMM_BLOCKS, 256>>>(gW + 4096, 1);
    gather_k<<<GW_BLOCKS, blk>>>(gb + 64, 1);

    dim3 g3(GEMM_BLOCKS, 3);
    gemm3_k<<<g3, 256>>>(bW, 0);
    gather3_k<<<GW3_BLOCKS, blk>>>(bb);
    gemm3_k<<<g3, 256>>>(bW, 1);
    gather3attn_k<<<GW_BLOCKS, blk>>>(bb);

    loss_k<<<(BATCH * 9 * 32 + T - 1) / T, blk>>>(bd, out);
}

// round 17
// speedup vs baseline: 1.1620x; 1.0526x over previous
#include <cuda_runtime.h>
#include <cuda_fp16.h>
#include <math.h>
#include <stdint.h>

#define N_USERS 60000
#define N_ITEMS 40000
#define NU      60001
#define NND     100002
#define NND4    ((NND + 3) / 4)
#define D       64
#define ND64    (NND * 64)
#define E_GLOBAL 1000000
#define E_BEH    500000
#define E_TOT   (E_GLOBAL + 3 * E_BEH)
#define BATCH    4096

#define SCB 512
#define NCH ((NND + SCB - 1) / SCB)

#define NB_CONCAT ((NND * 16 + 255) / 256)
#define NB_DEG    ((E_TOT / 4 + 255) / 256)
#define NB_MARK   ((BATCH * 9 + 255) / 256)
#define GEMM_BLOCKS ((NND + 127) / 128)
#define NB_FILL   ((E_TOT / 4 + 255) / 256)

/* ------- scratch. INVARIANT: g_deg, g_mark, g_sc, g_total zero at entry;
   restored by last readers. ------- */
__device__ __align__(16) __half g_hw[ND64];
__device__ __align__(16) __half g_hwb[3][ND64];
__device__ __align__(16) __half g_b16[ND64];
__device__ __align__(16) __half g_h16[ND64];
__device__ __align__(16) __half g_hb16[3][ND64];
__device__ __align__(16) __half g_beh16[3][ND64];
__device__ __align__(16) __half g_w16[3][ND64];
__device__ float  g_dinv[4 * NND];
__device__ int    g_deg[4 * NND];
__device__ int    g_ptr[4 * NND];
__device__ int    g_cnt[4 * NND];
__device__ int    g_csr[E_TOT];
__device__ int    g_mark[NND];
__device__ int    g_total[4];
__device__ float  g_sc[2];

/* ---------------- helpers ---------------- */
__device__ __forceinline__ float warp_sum(float v) {
#pragma unroll
    for (int o = 16; o; o >>= 1) v += __shfl_xor_sync(0xffffffffu, v, o);
    return v;
}
__device__ __forceinline__ float hsum8(float v) {
#pragma unroll
    for (int o = 4; o; o >>= 1) v += __shfl_xor_sync(0xffffffffu, v, o);
    return v;
}
__device__ __forceinline__ uint32_t f2h2(float2 v) {
    __half2 h = __floats2half2_rn(v.x, v.y);
    return *(uint32_t*)&h;
}
__device__ __forceinline__ float2 h22f2(uint32_t u) {
    return __half22float2(*(__half2*)&u);
}
__device__ __forceinline__ __half2 asH2(uint32_t u) { return *(__half2*)&u; }
__device__ __forceinline__ uint2 f4h4(float4 v) {
    return make_uint2(f2h2(make_float2(v.x, v.y)), f2h2(make_float2(v.z, v.w)));
}

__device__ __forceinline__ void mma16816(float4& c, uint32_t a0, uint32_t a1,
                                         uint32_t a2, uint32_t a3,
                                         uint32_t b0, uint32_t b1) {
    asm volatile(
        "mma.sync.aligned.m16n8k16.row.col.f32.f16.f16.f32 "
        "{%0,%1,%2,%3}, {%4,%5,%6,%7}, {%8,%9}, {%0,%1,%2,%3};"
        : "+f"(c.x), "+f"(c.y), "+f"(c.z), "+f"(c.w)
        : "r"(a0), "r"(a1), "r"(a2), "r"(a3), "r"(b0), "r"(b1));
}

/* ====== FUSED: concat+sumsq | degcnt | mark ====== */
__global__ __launch_bounds__(256) void init_fused_k(
    const float* __restrict__ ue, const float* __restrict__ ie,
    const int* __restrict__ aei, const int* __restrict__ bei,
    const int* __restrict__ bd) {
    int blk = blockIdx.x;
    if (blk < NB_CONCAT) {
        int t = blk * 256 + threadIdx.x;
        float su = 0.0f, si = 0.0f;
        if (t < NND * 16) {
            int node = t >> 4, q = t & 15;
            float4 v;
            if (node < NU) {
                v = ((const float4*)ue)[node * 16 + q];
                su = v.x * v.x + v.y * v.y + v.z * v.z + v.w * v.w;
            } else {
                v = ((const float4*)ie)[(node - NU) * 16 + q];
                si = v.x * v.x + v.y * v.y + v.z * v.z + v.w * v.w;
            }
            ((uint2*)g_b16)[t] = f4h4(v);
        }
        su = warp_sum(su);
        si = warp_sum(si);
        __shared__ float smu[8], smi[8];
        int w = threadIdx.x >> 5, l = threadIdx.x & 31;
        if (l == 0) { smu[w] = su; smi[w] = si; }
        __syncthreads();
        if (threadIdx.x == 0) {
            float a = 0.f, b = 0.f;
#pragma unroll
            for (int q = 0; q < 8; q++) { a += smu[q]; b += smi[q]; }
            if (a != 0.f) atomicAdd(&g_sc[0], a);
            if (b != 0.f) atomicAdd(&g_sc[1], b);
        }
    } else if (blk < NB_CONCAT + NB_DEG) {
        int q = (blk - NB_CONCAT) * 256 + threadIdx.x;
        if (q >= E_TOT / 4) return;
        int4 d4;
        int g;
        if (q < E_GLOBAL / 4) {
            g = 0;
            d4 = ((const int4*)(aei + E_GLOBAL))[q];
        } else {
            int r = q - E_GLOBAL / 4;
            int b = r / (E_BEH / 4), o = r - b * (E_BEH / 4);
            g = 1 + b;
            d4 = ((const int4*)(bei + (b * 2 + 1) * E_BEH))[o];
        }
        int* deg = g_deg + g * NND;
        atomicAdd(&deg[d4.x], 1);
        atomicAdd(&deg[d4.y], 1);
        atomicAdd(&deg[d4.z], 1);
        atomicAdd(&deg[d4.w], 1);
    } else {
        int t = (blk - NB_CONCAT - NB_DEG) * 256 + threadIdx.x;
        if (t >= BATCH * 9) return;
        int k = t / 9, r = t - k * 9;
        int i = r / 3, c = r - i * 3;
        int val = bd[k * 9 + i * 3 + c];
        if (c == 0) g_mark[val] = 1;
        else        g_mark[NU + val] = 1;
    }
}

/* ---- single-kernel CSR allocation ---- */
__global__ __launch_bounds__(SCB) void alloc_k(float* out) {
    __shared__ int sm[SCB];
    __shared__ int sbase;
    int b = blockIdx.x;
    int g = b / NCH, ch = b % NCH;
    int idx = ch * SCB + threadIdx.x;
    if (b == 0 && threadIdx.x == 0) out[0] = 0.0f;
    int v = (idx < NND) ? g_deg[g * NND + idx] : 0;
    sm[threadIdx.x] = v;
    __syncthreads();
    for (int o = 1; o < SCB; o <<= 1) {
        int add = (threadIdx.x >= o) ? sm[threadIdx.x - o] : 0;
        __syncthreads();
        sm[threadIdx.x] += add;
        __syncthreads();
    }
    if (threadIdx.x == SCB - 1) sbase = atomicAdd(&g_total[g], sm[SCB - 1]);
    __syncthreads();
    int beg = sbase + sm[threadIdx.x] - v;
    if (idx < NND) {
        g_ptr[g * NND + idx]  = beg;
        g_cnt[g * NND + idx]  = beg;
        g_dinv[g * NND + idx] = (v > 0) ? rsqrtf((float)v) : 0.0f;
        g_deg[g * NND + idx]  = 0;
    }
}

/* --------- HMMA GEMM body --------- */
#define SAS 72
__device__ __forceinline__ void gemm_body(const __half* __restrict__ A16,
                                          const float* __restrict__ W,
                                          __half* __restrict__ HW, int row0,
                                          const float* __restrict__ dv) {
    __shared__ __half sA[128 * SAS];
    __shared__ __half sWt[64 * SAS];
    int tid = threadIdx.x;

#pragma unroll
    for (int i = 0; i < 4; i++) {
        int idx = tid + i * 256;
        int r = idx >> 3, c8 = idx & 7;
        uint4 u = make_uint4(0u, 0u, 0u, 0u);
        int row = row0 + r;
        if (row < NND) u = ((const uint4*)A16)[row * 8 + c8];
        *(uint4*)(sA + r * SAS + c8 * 8) = u;
    }
#pragma unroll
    for (int i = 0; i < 4; i++) {
        int idx = tid + i * 256;
        int k = idx >> 4, n4 = (idx & 15) * 4;
        float4 w = ((const float4*)W)[idx];
        sWt[(n4 + 0) * SAS + k] = __float2half_rn(w.x);
        sWt[(n4 + 1) * SAS + k] = __float2half_rn(w.y);
        sWt[(n4 + 2) * SAS + k] = __float2half_rn(w.z);
        sWt[(n4 + 3) * SAS + k] = __float2half_rn(w.w);
    }
    __syncthreads();

    int wid = tid >> 5, lane = tid & 31;
    int gq = lane >> 2, tg = lane & 3;
    int mrow = wid * 16;

    float4 acc[8];
#pragma unroll
    for (int n = 0; n < 8; n++) acc[n] = make_float4(0.f, 0.f, 0.f, 0.f);

#pragma unroll
    for (int ks = 0; ks < 4; ks++) {
        int k0 = ks * 16 + tg * 2;
        uint32_t a0 = *(uint32_t*)(sA + (mrow + gq) * SAS + k0);
        uint32_t a1 = *(uint32_t*)(sA + (mrow + gq + 8) * SAS + k0);
        uint32_t a2 = *(uint32_t*)(sA + (mrow + gq) * SAS + k0 + 8);
        uint32_t a3 = *(uint32_t*)(sA + (mrow + gq + 8) * SAS + k0 + 8);
#pragma unroll
        for (int n = 0; n < 8; n++) {
            uint32_t b0 = *(uint32_t*)(sWt + (n * 8 + gq) * SAS + k0);
            uint32_t b1 = *(uint32_t*)(sWt + (n * 8 + gq) * SAS + k0 + 8);
            mma16816(acc[n], a0, a1, a2, a3, b0, b1);
        }
    }

    int r0 = row0 + mrow + gq;
    int r1 = r0 + 8;
    float s0 = (r0 < NND) ? dv[r0] : 0.0f;
    float s1 = (r1 < NND) ? dv[r1] : 0.0f;
#pragma unroll
    for (int n = 0; n < 8; n++) {
        int col = n * 8 + tg * 2;
        if (r0 < NND)
            *(uint32_t*)(HW + r0 * 64 + col) = f2h2(make_float2(acc[n].x * s0, acc[n].y * s0));
        if (r1 < NND)
            *(uint32_t*)(HW + r1 * 64 + col) = f2h2(make_float2(acc[n].z * s1, acc[n].w * s1));
    }
}

/* ====== FUSED: global layer-1 GEMM | fill ====== */
__global__ __launch_bounds__(256) void fill_gemm_k(
    const int* __restrict__ aei, const int* __restrict__ bei,
    const float* __restrict__ gW) {
    if (blockIdx.x < GEMM_BLOCKS) {
        gemm_body(g_b16, gW, g_hw, blockIdx.x * 128, g_dinv);
        return;
    }
    int q = (blockIdx.x - GEMM_BLOCKS) * 256 + threadIdx.x;
    if (q >= E_TOT / 4) return;
    int4 s4, d4;
    int g, base;
    if (q < E_GLOBAL / 4) {
        g = 0;
        base = 0;
        s4 = ((const int4*)aei)[q];
        d4 = ((const int4*)(aei + E_GLOBAL))[q];
    } else {
        int r = q - E_GLOBAL / 4;
        int b = r / (E_BEH / 4), o = r - b * (E_BEH / 4);
        g = 1 + b;
        base = E_GLOBAL + b * E_BEH;
        s4 = ((const int4*)(bei + (b * 2) * E_BEH))[o];
        d4 = ((const int4*)(bei + (b * 2 + 1) * E_BEH))[o];
    }
    int* cnt = g_cnt + g * NND;
    int* csr = g_csr + base;
    csr[atomicAdd(&cnt[d4.x], 1)] = s4.x;
    csr[atomicAdd(&cnt[d4.y], 1)] = s4.y;
    csr[atomicAdd(&cnt[d4.z], 1)] = s4.z;
    csr[atomicAdd(&cnt[d4.w], 1)] = s4.w;
}

__global__ __launch_bounds__(256) void gemm_k(const float* __restrict__ W, int srcsel) {
    gemm_body(srcsel ? g_h16 : g_b16, W, g_hw, blockIdx.x * 128, g_dinv);
}

__global__ __launch_bounds__(256) void gemm3_k(const float* __restrict__ bW, int l) {
    int b = blockIdx.y;
    const __half* A16 = l ? g_hb16[b] : g_b16;
    gemm_body(A16, bW + (b * 2 + l) * 4096, g_hwb[b], blockIdx.x * 128,
              g_dinv + (1 + b) * NND);
}

/* ------- gather core: 8 lanes/node, HADD2 tree over groups of 4 edges ------- */
struct F8 { float v[8]; };

/* fp16 tree-sum of 4 rows, then one fp32 accumulate (28 ops vs 64) */
#define HACC4(U0, U1, U2, U3)                                              \
    do {                                                                   \
        __half2 t0 = __hadd2(__hadd2(asH2((U0).x), asH2((U1).x)),          \
                             __hadd2(asH2((U2).x), asH2((U3).x)));         \
        __half2 t1 = __hadd2(__hadd2(asH2((U0).y), asH2((U1).y)),          \
                             __hadd2(asH2((U2).y), asH2((U3).y)));         \
        __half2 t2 = __hadd2(__hadd2(asH2((U0).z), asH2((U1).z)),          \
                             __hadd2(asH2((U2).z), asH2((U3).z)));         \
        __half2 t3 = __hadd2(__hadd2(asH2((U0).w), asH2((U1).w)),          \
                             __hadd2(asH2((U2).w), asH2((U3).w)));         \
        float2 f0 = __half22float2(t0), f1 = __half22float2(t1);           \
        float2 f2 = __half22float2(t2), f3 = __half22float2(t3);           \
        acc[0] += f0.x; acc[1] += f0.y; acc[2] += f1.x; acc[3] += f1.y;    \
        acc[4] += f2.x; acc[5] += f2.y; acc[6] += f3.x; acc[7] += f3.y;    \
    } while (0)

#define ACC1(U)                                                            \
    do {                                                                   \
        float2 p0 = h22f2((U).x), p1 = h22f2((U).y);                       \
        float2 p2 = h22f2((U).z), p3 = h22f2((U).w);                       \
        acc[0] += p0.x; acc[1] += p0.y; acc[2] += p1.x; acc[3] += p1.y;    \
        acc[4] += p2.x; acc[5] += p2.y; acc[6] += p3.x; acc[7] += p3.y;    \
    } while (0)

__device__ __forceinline__ F8 gather_core8(
    const __half* __restrict__ HW, int csr_base, int g,
    const float* __restrict__ bias, int node, int sub, bool active) {

    const int* csr = g_csr + csr_base;
    const uint4* HW128 = (const uint4*)HW;
    int beg = 0, end = 0;
    if (active) {
        beg = g_ptr[g * NND + node];
        end = g_cnt[g * NND + node];
    }

    float acc[8] = {};
    int k = beg;
    if (k + 4 <= end) {
        int i0 = csr[k], i1 = csr[k + 1], i2 = csr[k + 2], i3 = csr[k + 3];
        k += 4;
        uint4 u0 = HW128[i0 * 8 + sub];
        uint4 u1 = HW128[i1 * 8 + sub];
        uint4 u2 = HW128[i2 * 8 + sub];
        uint4 u3 = HW128[i3 * 8 + sub];
        while (k + 4 <= end) {
            int j0 = csr[k], j1 = csr[k + 1], j2 = csr[k + 2], j3 = csr[k + 3];
            k += 4;
            HACC4(u0, u1, u2, u3);
            u0 = HW128[j0 * 8 + sub];
            u1 = HW128[j1 * 8 + sub];
            u2 = HW128[j2 * 8 + sub];
            u3 = HW128[j3 * 8 + sub];
        }
        HACC4(u0, u1, u2, u3);
    }
    for (; k < end; k++) {
        uint4 u = HW128[csr[k] * 8 + sub];
        ACC1(u);
    }

    float dd = active ? g_dinv[g * NND + node] : 0.0f;
    float4 bv0 = ((const float4*)bias)[sub * 2];
    float4 bv1 = ((const float4*)bias)[sub * 2 + 1];
    F8 o;
    o.v[0] = acc[0] * dd + bv0.x; o.v[1] = acc[1] * dd + bv0.y;
    o.v[2] = acc[2] * dd + bv0.z; o.v[3] = acc[3] * dd + bv0.w;
    o.v[4] = acc[4] * dd + bv1.x; o.v[5] = acc[5] * dd + bv1.y;
    o.v[6] = acc[6] * dd + bv1.z; o.v[7] = acc[7] * dd + bv1.w;
    float ss = 0.f;
#pragma unroll
    for (int i = 0; i < 8; i++) ss += o.v[i] * o.v[i];
    ss = hsum8(ss);
    float inv = 1.0f / fmaxf(sqrtf(ss), 1e-12f);
#pragma unroll
    for (int i = 0; i < 8; i++) o.v[i] *= inv;
    return o;
}

__device__ __forceinline__ uint4 f8h8(const F8& h) {
    uint4 r;
    r.x = f2h2(make_float2(h.v[0], h.v[1]));
    r.y = f2h2(make_float2(h.v[2], h.v[3]));
    r.z = f2h2(make_float2(h.v[4], h.v[5]));
    r.w = f2h2(make_float2(h.v[6], h.v[7]));
    return r;
}
__device__ __forceinline__ F8 h8f8(uint4 u) {
    F8 r;
    float2 p0 = h22f2(u.x), p1 = h22f2(u.y);
    float2 p2 = h22f2(u.z), p3 = h22f2(u.w);
    r.v[0] = p0.x; r.v[1] = p0.y; r.v[2] = p1.x; r.v[3] = p1.y;
    r.v[4] = p2.x; r.v[5] = p2.y; r.v[6] = p3.x; r.v[7] = p3.y;
    return r;
}

/* global gather: 4 nodes/warp; base fp16 in-place */
__global__ __launch_bounds__(256) void gather_k(const float* __restrict__ bias, int mode) {
    int t = blockIdx.x * blockDim.x + threadIdx.x;
    int w = t >> 5, lane = t & 31;
    if (w >= NND4) return;
    int sub = lane & 7;
    int node = w * 4 + (lane >> 3);
    bool act = node < NND;
    F8 h = gather_core8(g_hw, 0, 0, bias, node, sub, act);
    if (!act) return;
    int offq = node * 8 + sub;
    F8 r = h8f8(((const uint4*)g_b16)[offq]);
    float sc = (mode == 0) ? 1.0f : 0.5f;
    F8 nb;
#pragma unroll
    for (int i = 0; i < 8; i++) nb.v[i] = r.v[i] + sc * h.v[i];
    ((uint4*)g_b16)[offq] = f8h8(nb);
    if (mode == 0) ((uint4*)g_h16)[offq] = f8h8(h);
}

/* behavioral layer 0 gather; res stored only for marked nodes */
__global__ __launch_bounds__(256) void gather3_k(const float* __restrict__ bb) {
    int t = blockIdx.x * blockDim.x + threadIdx.x;
    int w = t >> 5, lane = t & 31;
    if (w >= 3 * NND4) return;
    int b = w / NND4, i = w - b * NND4;
    int sub = lane & 7;
    int node = i * 4 + (lane >> 3);
    bool act = node < NND;
    F8 h = gather_core8(g_hwb[b], E_GLOBAL + b * E_BEH, 1 + b,
                        bb + (b * 2) * 64, node, sub, act);
    if (!act) return;
    int offq = node * 8 + sub;
    ((uint4*)g_hb16[b])[offq] = f8h8(h);
    if (g_mark[node]) {
        F8 r = h8f8(((const uint4*)g_b16)[offq]);
        F8 res;
#pragma unroll
        for (int j = 0; j < 8; j++) res.v[j] = r.v[j] + h.v[j];
        ((uint4*)g_beh16[b])[offq] = f8h8(res);
    }
}

/* behavioral layer 1 gather + attention + combine — marked nodes; unmarks */
__global__ __launch_bounds__(256) void gather3attn_k(const float* __restrict__ bb) {
    int t = blockIdx.x * blockDim.x + threadIdx.x;
    int w = t >> 5, lane = t & 31;
    if (w >= NND4) return;
    int sub = lane & 7;
    int node = w * 4 + (lane >> 3);
    bool act = (node < NND) && (g_mark[node] != 0);
    if (__ballot_sync(0xffffffffu, act) == 0u) return;
    int offq = node * 8 + sub;

    F8 tok[3];
#pragma unroll
    for (int b = 0; b < 3; b++) {
        F8 h = gather_core8(g_hwb[b], E_GLOBAL + b * E_BEH, 1 + b,
                            bb + (b * 2 + 1) * 64, node, sub, act);
        F8 r = {};
        if (act) r = h8f8(((const uint4*)g_beh16[b])[offq]);
#pragma unroll
        for (int i = 0; i < 8; i++) tok[b].v[i] = r.v[i] + 0.5f * h.v[i];
    }

    float d00 = 0.f, d01 = 0.f, d02 = 0.f, d11 = 0.f, d12 = 0.f, d22 = 0.f;
#pragma unroll
    for (int i = 0; i < 8; i++) {
        d00 += tok[0].v[i] * tok[0].v[i];
        d01 += tok[0].v[i] * tok[1].v[i];
        d02 += tok[0].v[i] * tok[2].v[i];
        d11 += tok[1].v[i] * tok[1].v[i];
        d12 += tok[1].v[i] * tok[2].v[i];
        d22 += tok[2].v[i] * tok[2].v[i];
    }
    float s00 = hsum8(d00), s01 = hsum8(d01), s02 = hsum8(d02);
    float s11 = hsum8(d11), s12 = hsum8(d12), s22 = hsum8(d22);

    if (!act) return;

    const float sc = 0.125f;
    float s[3][3] = {{s00 * sc, s01 * sc, s02 * sc},
                     {s01 * sc, s11 * sc, s12 * sc},
                     {s02 * sc, s12 * sc, s22 * sc}};

    bool isU = node < NU;
    float gw = isU ? 2.35f : 1.0f;
    float bw = isU ? 0.242f : 0.55f;
    F8 gvv = h8f8(((const uint4*)g_b16)[offq]);

#pragma unroll
    for (int b = 0; b < 3; b++) {
        float m  = fmaxf(s[b][0], fmaxf(s[b][1], s[b][2]));
        float e0 = __expf(s[b][0] - m), e1 = __expf(s[b][1] - m), e2 = __expf(s[b][2] - m);
        float is = 1.0f / (e0 + e1 + e2);
        float a0 = e0 * is, a1 = e1 * is, a2 = e2 * is;
        F8 o;
#pragma unroll
        for (int i = 0; i < 8; i++)
            o.v[i] = gw * gvv.v[i] + bw * (a0 * tok[0].v[i] + a1 * tok[1].v[i] + a2 * tok[2].v[i]);
        ((uint4*)g_w16[b])[offq] = f8h8(o);
    }
    if (sub == 0) g_mark[node] = 0;
}

/* ---------------- BPR loss + regularizer; restores g_sc, g_total ---------------- */
__global__ void loss_k(const int* __restrict__ bd, float* out) {
    int t = blockIdx.x * blockDim.x + threadIdx.x;
    int w = t >> 5, lane = t & 31;
    float partial = 0.0f;
    if (w < BATCH * 9) {
        int k = w / 9, pr = w - k * 9;
        int i = pr / 3, j = pr - i * 3;
        int u   = bd[k * 9 + i * 3 + 0];
        int ip  = bd[k * 9 + i * 3 + 1];
        int in_ = bd[k * 9 + i * 3 + 2];
        float2 uu = h22f2(((const uint32_t*)g_w16[i])[u * 32 + lane]);
        float2 pp = h22f2(((const uint32_t*)g_w16[j])[(NU + ip) * 32 + lane]);
        float2 nn = h22f2(((const uint32_t*)g_w16[j])[(NU + in_) * 32 + lane]);
        float sp = warp_sum(uu.x * pp.x + uu.y * pp.y);
        float sn = warp_sum(uu.x * nn.x + uu.y * nn.y);
        float x  = sp - sn;
        float ls = fminf(x, 0.0f) - log1pf(expf(-fabsf(x)));
        partial = -ls * (1.0f / (float)BATCH);
    }
    __shared__ float sm[8];
    if (lane == 0) sm[threadIdx.x >> 5] = partial;
    __syncthreads();
    if (threadIdx.x == 0) {
        float s = 0.0f;
#pragma unroll
        for (int q = 0; q < 8; q++) s += sm[q];
        if (blockIdx.x == 0) {
            s += 0.001f * ((sqrtf(g_sc[0]) + sqrtf(g_sc[1])) / (float)(N_ITEMS + 1));
            g_sc[0] = 0.0f;
            g_sc[1] = 0.0f;
            g_total[0] = 0; g_total[1] = 0; g_total[2] = 0; g_total[3] = 0;
        }
        atomicAdd(out, s);
    }
}

/* ================================ launch ================================ */
extern "C" void kernel_launch(void* const* d_in, const int* in_sizes, int n_in,
                              void* d_out, int out_size) {
    const float* ue  = (const float*)d_in[0];
    const float* ie  = (const float*)d_in[1];
    const float* gW  = (const float*)d_in[2];
    const float* gb  = (const float*)d_in[3];
    const float* bW  = (const float*)d_in[4];
    const float* bb  = (const float*)d_in[5];
    const int*   aei = (const int*)d_in[6];
    const int*   bei = (const int*)d_in[7];
    const int*   bd  = (const int*)d_in[8];
    float* out = (float*)d_out;

    const int T = 256;
    dim3 blk(T);

    init_fused_k<<<NB_CONCAT + NB_DEG + NB_MARK, blk>>>(ue, ie, aei, bei, bd);
    alloc_k<<<4 * NCH, SCB>>>(out);
    fill_gemm_k<<<GEMM_BLOCKS + NB_FILL, blk>>>(aei, bei, gW);

    const int GW_BLOCKS  = (NND4 * 32 + T - 1) / T;
    const int GW3_BLOCKS = (3 * NND4 * 32 + T - 1) / T;

    gather_k<<<GW_BLOCKS, blk>>>(gb, 0);
    gemm_k<<<GEMM_BLOCKS, 256>>>(gW + 4096, 1);
    gather_k<<<GW_BLOCKS, blk>>>(gb + 64, 1);

    dim3 g3(GEMM_BLOCKS, 3);
    gemm3_k<<<g3, 256>>>(bW, 0);
    gather3_k<<<GW3_BLOCKS, blk>>>(bb);
    gemm3_k<<<g3, 256>>>(bW, 1);
    gather3attn_k<<<GW_BLOCKS, blk>>>(bb);

    loss_k<<<(BATCH * 9 * 32 + T - 1) / T, blk>>>(bd, out);
}